// round 1
// baseline (speedup 1.0000x reference)
#include <cuda_runtime.h>
#include <math.h>
#include <stddef.h>

// Problem constants
#define TB 2
#define TT 2048
#define NE 1024
#define NH 16
#define HD 64
#define C3 (3 * NE)   // 3072

// Scratch (allocation-free rule: device globals)
__device__ float g_kqv[(size_t)TB * TT * C3];   // [B*T, 3C]  (k | q | v)
__device__ float g_attn[(size_t)TB * TT * NE];  // [B*T, C]   attention output

// ---------------------------------------------------------------------------
// SGEMM NT:  C[m,n] = sum_k A[m,k] * W[n,k] (+ bias[n])
// A: [M,K] row-major, W: [N,K] row-major. 128x128x16 tiles, 8x8 per thread.
// M,N,K all multiples of 128/128/16 for this problem (no bounds checks).
// ---------------------------------------------------------------------------
__global__ __launch_bounds__(256)
void sgemm_nt(const float* __restrict__ A, const float* __restrict__ W,
              const float* __restrict__ bias, float* __restrict__ Cout,
              int M, int N, int K)
{
    const int BM = 128, BN = 128, BK = 16;
    __shared__ float As[BK][BM + 4];   // +4 pad: transpose-store conflicts -> 2-way
    __shared__ float Bs[BK][BN + 4];

    const int tid  = threadIdx.x;
    const int brow = blockIdx.y * BM;
    const int bcol = blockIdx.x * BN;

    // global->smem load mapping: 2 float4 rows per thread per operand
    const int lr = tid >> 2;          // 0..63
    const int lc = (tid & 3) * 4;     // 0,4,8,12

    // compute mapping: 16x16 thread grid, 8x8 micro-tile
    const int tr = (tid >> 4) * 8;
    const int tc = (tid & 15) * 8;

    float acc[8][8];
#pragma unroll
    for (int i = 0; i < 8; i++)
#pragma unroll
        for (int j = 0; j < 8; j++) acc[i][j] = 0.f;

    for (int kk = 0; kk < K; kk += BK) {
#pragma unroll
        for (int it = 0; it < 2; it++) {
            int r = lr + it * 64;
            float4 av = *(const float4*)&A[(size_t)(brow + r) * K + kk + lc];
            As[lc + 0][r] = av.x; As[lc + 1][r] = av.y;
            As[lc + 2][r] = av.z; As[lc + 3][r] = av.w;
            float4 bv = *(const float4*)&W[(size_t)(bcol + r) * K + kk + lc];
            Bs[lc + 0][r] = bv.x; Bs[lc + 1][r] = bv.y;
            Bs[lc + 2][r] = bv.z; Bs[lc + 3][r] = bv.w;
        }
        __syncthreads();

#pragma unroll
        for (int k = 0; k < BK; k++) {
            float ra[8], rb[8];
            *(float4*)&ra[0] = *(const float4*)&As[k][tr];
            *(float4*)&ra[4] = *(const float4*)&As[k][tr + 4];
            *(float4*)&rb[0] = *(const float4*)&Bs[k][tc];
            *(float4*)&rb[4] = *(const float4*)&Bs[k][tc + 4];
#pragma unroll
            for (int i = 0; i < 8; i++)
#pragma unroll
                for (int j = 0; j < 8; j++)
                    acc[i][j] = fmaf(ra[i], rb[j], acc[i][j]);
        }
        __syncthreads();
    }

#pragma unroll
    for (int i = 0; i < 8; i++) {
#pragma unroll
        for (int j = 0; j < 8; j += 4) {
            float4 o;
            o.x = acc[i][j + 0]; o.y = acc[i][j + 1];
            o.z = acc[i][j + 2]; o.w = acc[i][j + 3];
            if (bias) {
                o.x += bias[bcol + tc + j + 0];
                o.y += bias[bcol + tc + j + 1];
                o.z += bias[bcol + tc + j + 2];
                o.w += bias[bcol + tc + j + 3];
            }
            *(float4*)&Cout[(size_t)(brow + tr + i) * N + bcol + tc + j] = o;
        }
    }
}

// ---------------------------------------------------------------------------
// Flash attention (fp32, online softmax). One CTA per (b, h, 64-row q tile).
// K/V tiles of 64 rows; causal blocks above the diagonal skipped.
// smem: sQ[d][r], sK[d][c] (transposed, stride 65), sV[c][d], sP[c][r].
// 256 threads; 16x16 thread grid; 4x4 micro-tile for S and O.
// ---------------------------------------------------------------------------
#define ATTN_SMEM (4 * 64 * 65 * (int)sizeof(float))

__global__ __launch_bounds__(256)
void attn_kernel()
{
    const int qt = blockIdx.x;   // 0..31
    const int h  = blockIdx.y;   // 0..15
    const int b  = blockIdx.z;   // 0..1

    extern __shared__ float smem[];
    float* sQ = smem;                 // [64][65]  sQ[d*65 + r]
    float* sK = sQ + 64 * 65;         // [64][65]  sK[d*65 + c]
    float* sV = sK + 64 * 65;         // [64][65]  sV[c*65 + d]
    float* sP = sV + 64 * 65;         // [64][65]  sP[c*65 + r]

    const int tid = threadIdx.x;
    const int tx  = tid & 15;
    const int ty  = tid >> 4;
    const int r0  = ty * 4;
    const int c0  = tx * 4;
    const int qbase = qt * 64;

    const float* base = g_kqv + (size_t)b * TT * C3 + h * HD;
    const float* kptr = base;               // k is first in kqv
    const float* qptr = base + NE;          // q second
    const float* vptr = base + 2 * NE;      // v third

    // Load Q tile transposed: sQ[d][r]
    {
        const int t  = tid >> 4;          // 0..15
        const int d4 = (tid & 15) * 4;
#pragma unroll
        for (int it = 0; it < 4; it++) {
            int row = it * 16 + t;
            float4 v = *(const float4*)(qptr + (size_t)(qbase + row) * C3 + d4);
            sQ[(d4 + 0) * 65 + row] = v.x;
            sQ[(d4 + 1) * 65 + row] = v.y;
            sQ[(d4 + 2) * 65 + row] = v.z;
            sQ[(d4 + 3) * 65 + row] = v.w;
        }
    }

    float m_i[4], l_i[4], acc[4][4];
#pragma unroll
    for (int i = 0; i < 4; i++) {
        m_i[i] = -1e30f; l_i[i] = 0.f;
#pragma unroll
        for (int j = 0; j < 4; j++) acc[i][j] = 0.f;
    }

    const float scale = 0.125f;  // 1/sqrt(64)

    for (int kt = 0; kt <= qt; ++kt) {
        const int kbase = kt * 64;
        __syncthreads();  // protect sK/sV from previous-iter readers

        // Load K transposed + V natural
        {
            const int t  = tid >> 4;
            const int d4 = (tid & 15) * 4;
#pragma unroll
            for (int it = 0; it < 4; it++) {
                int row = it * 16 + t;
                float4 kv = *(const float4*)(kptr + (size_t)(kbase + row) * C3 + d4);
                sK[(d4 + 0) * 65 + row] = kv.x;
                sK[(d4 + 1) * 65 + row] = kv.y;
                sK[(d4 + 2) * 65 + row] = kv.z;
                sK[(d4 + 3) * 65 + row] = kv.w;
                float4 vv = *(const float4*)(vptr + (size_t)(kbase + row) * C3 + d4);
                sV[row * 65 + d4 + 0] = vv.x;
                sV[row * 65 + d4 + 1] = vv.y;
                sV[row * 65 + d4 + 2] = vv.z;
                sV[row * 65 + d4 + 3] = vv.w;
            }
        }
        __syncthreads();

        // S = Q K^T  (4x4 per thread)
        float s[4][4];
#pragma unroll
        for (int i = 0; i < 4; i++)
#pragma unroll
            for (int j = 0; j < 4; j++) s[i][j] = 0.f;

#pragma unroll 4
        for (int d = 0; d < 64; d++) {
            float rq[4], rk[4];
#pragma unroll
            for (int i = 0; i < 4; i++) rq[i] = sQ[d * 65 + r0 + i];
#pragma unroll
            for (int j = 0; j < 4; j++) rk[j] = sK[d * 65 + c0 + j];
#pragma unroll
            for (int i = 0; i < 4; i++)
#pragma unroll
                for (int j = 0; j < 4; j++)
                    s[i][j] = fmaf(rq[i], rk[j], s[i][j]);
        }

        // scale + causal mask (only the diagonal block is partial)
        if (kt == qt) {
#pragma unroll
            for (int i = 0; i < 4; i++)
#pragma unroll
                for (int j = 0; j < 4; j++)
                    s[i][j] = (c0 + j <= r0 + i) ? s[i][j] * scale : -1e30f;
        } else {
#pragma unroll
            for (int i = 0; i < 4; i++)
#pragma unroll
                for (int j = 0; j < 4; j++) s[i][j] *= scale;
        }

        // row max across 16 tx-threads (same half-warp)
        float rmax[4];
#pragma unroll
        for (int i = 0; i < 4; i++) {
            rmax[i] = fmaxf(fmaxf(s[i][0], s[i][1]), fmaxf(s[i][2], s[i][3]));
        }
#pragma unroll
        for (int off = 8; off >= 1; off >>= 1) {
#pragma unroll
            for (int i = 0; i < 4; i++)
                rmax[i] = fmaxf(rmax[i], __shfl_xor_sync(0xffffffffu, rmax[i], off));
        }

        float mnew[4], alpha[4], rsum[4];
#pragma unroll
        for (int i = 0; i < 4; i++) {
            mnew[i]  = fmaxf(m_i[i], rmax[i]);
            alpha[i] = __expf(m_i[i] - mnew[i]);
            rsum[i]  = 0.f;
        }

        float p[4][4];
#pragma unroll
        for (int i = 0; i < 4; i++)
#pragma unroll
            for (int j = 0; j < 4; j++) {
                p[i][j] = __expf(s[i][j] - mnew[i]);
                rsum[i] += p[i][j];
            }
#pragma unroll
        for (int off = 8; off >= 1; off >>= 1) {
#pragma unroll
            for (int i = 0; i < 4; i++)
                rsum[i] += __shfl_xor_sync(0xffffffffu, rsum[i], off);
        }
#pragma unroll
        for (int i = 0; i < 4; i++) {
            l_i[i] = l_i[i] * alpha[i] + rsum[i];
            m_i[i] = mnew[i];
#pragma unroll
            for (int j = 0; j < 4; j++) acc[i][j] *= alpha[i];
        }

        // write P (transposed: sP[c][r])
#pragma unroll
        for (int i = 0; i < 4; i++)
#pragma unroll
            for (int j = 0; j < 4; j++)
                sP[(c0 + j) * 65 + r0 + i] = p[i][j];
        __syncthreads();

        // O += P V  (O columns == d, same c0 split)
#pragma unroll 4
        for (int c = 0; c < 64; c++) {
            float rp[4], rv[4];
#pragma unroll
            for (int i = 0; i < 4; i++) rp[i] = sP[c * 65 + r0 + i];
#pragma unroll
            for (int j = 0; j < 4; j++) rv[j] = sV[c * 65 + c0 + j];
#pragma unroll
            for (int i = 0; i < 4; i++)
#pragma unroll
                for (int j = 0; j < 4; j++)
                    acc[i][j] = fmaf(rp[i], rv[j], acc[i][j]);
        }
    }

    // epilogue: O / l  -> g_attn[b, t, h*64 + d]
#pragma unroll
    for (int i = 0; i < 4; i++) {
        float inv = 1.0f / l_i[i];
        float4 o;
        o.x = acc[i][0] * inv; o.y = acc[i][1] * inv;
        o.z = acc[i][2] * inv; o.w = acc[i][3] * inv;
        *(float4*)&g_attn[((size_t)b * TT + qbase + r0 + i) * NE + h * HD + c0] = o;
    }
}

// ---------------------------------------------------------------------------
// Launch
// ---------------------------------------------------------------------------
extern "C" void kernel_launch(void* const* d_in, const int* in_sizes, int n_in,
                              void* d_out, int out_size)
{
    // Defensive input matching by element count (metadata order: x, W_kqv, W_proj, b_proj)
    const float* x = nullptr, *Wkqv = nullptr, *Wproj = nullptr, *bproj = nullptr;
    for (int i = 0; i < n_in; i++) {
        int sz = in_sizes[i];
        if      (sz == TB * TT * NE)      x     = (const float*)d_in[i];
        else if (sz == 3 * NE * NE)       Wkqv  = (const float*)d_in[i];
        else if (sz == NE * NE)           Wproj = (const float*)d_in[i];
        else if (sz == NE)                bproj = (const float*)d_in[i];
    }
    float* out = (float*)d_out;

    float* kqv  = nullptr;
    float* attn = nullptr;
    cudaGetSymbolAddress((void**)&kqv,  g_kqv);
    cudaGetSymbolAddress((void**)&attn, g_attn);

    cudaFuncSetAttribute(attn_kernel,
                         cudaFuncAttributeMaxDynamicSharedMemorySize, ATTN_SMEM);

    const int M = TB * TT;  // 4096

    // 1) KQV projection: [4096,1024] @ [3072,1024]^T -> [4096,3072]
    {
        dim3 grid(C3 / 128, M / 128);
        sgemm_nt<<<grid, 256>>>(x, Wkqv, nullptr, kqv, M, C3, NE);
    }

    // 2) Causal flash attention
    {
        dim3 grid(TT / 64, NH, TB);
        attn_kernel<<<grid, 256, ATTN_SMEM>>>();
    }

    // 3) Output projection + bias: [4096,1024] @ [1024,1024]^T + b -> out
    {
        dim3 grid(NE / 128, M / 128);
        sgemm_nt<<<grid, 256>>>(attn, Wproj, bproj, out, M, NE, NE);
    }
}

// round 3
// speedup vs baseline: 1.3240x; 1.3240x over previous
#include <cuda_runtime.h>
#include <cuda_bf16.h>
#include <math.h>
#include <stddef.h>
#include <stdint.h>

// Problem constants
#define TB 2
#define TT 2048
#define NE 1024
#define NH 16
#define HD 64
#define C3 (3 * NE)   // 3072

// Scratch (allocation-free rule: device globals)
__device__ float g_kqv[(size_t)TB * TT * C3];   // [B*T, 3C]  (k | q | v)
__device__ float g_attn[(size_t)TB * TT * NE];  // [B*T, C]   attention output

// ===========================================================================
// mma.sync m16n8k16 bf16 -> f32  (standard PTX, works at compute_103)
// ===========================================================================
static __device__ __forceinline__ void mma16816(float* d, const uint4& a, const uint2& b) {
    asm volatile(
        "mma.sync.aligned.m16n8k16.row.col.f32.bf16.bf16.f32 "
        "{%0,%1,%2,%3}, {%4,%5,%6,%7}, {%8,%9}, {%0,%1,%2,%3};"
        : "+f"(d[0]), "+f"(d[1]), "+f"(d[2]), "+f"(d[3])
        : "r"(a.x), "r"(a.y), "r"(a.z), "r"(a.w), "r"(b.x), "r"(b.y));
}

// fp32 pair -> packed bf16 hi + packed bf16 lo  (x = hi + lo)
static __device__ __forceinline__ void split2(float2 f, uint32_t& h, uint32_t& l) {
    __nv_bfloat162 hp = __floats2bfloat162_rn(f.x, f.y);
    float2 hf = __bfloat1622float2(hp);
    __nv_bfloat162 lp = __floats2bfloat162_rn(f.x - hf.x, f.y - hf.y);
    h = *reinterpret_cast<uint32_t*>(&hp);
    l = *reinterpret_cast<uint32_t*>(&lp);
}

// ===========================================================================
// GEMM-NT via mma.sync:  C[m,n] = sum_k A[m,k] * W[n,k] (+ bias[n])
// fp32 in/out, bf16 hi/lo 3-MMA split, f32 accumulate.
// CTA tile 128x128, BK=32, 256 threads = 8 warps (2 M x 4 N), warp tile 64x32.
//
// Smem is FRAGMENT-MAJOR: A frag (m16k16) = [32 lanes][uint4], B frag (k16n8)
// = [32 lanes][uint2], stored exactly in mma register layout. Writers compute
// the hi/lo split and place data so consumers do one LDS.128 / LDS.64 per
// fragment with consecutive lanes (conflict-free).
//
// Stage layout (32 KB):
//   [0      ) Ah : 16 frags (mf 0..7, kf 0..1) x 512B
//   [8192   ) Al
//   [16384  ) Bh : 32 frags (nf 0..15, kf 0..1) x 256B
//   [24576  ) Bl
// Double buffered: 64 KB total.
// ===========================================================================
#define GSTAGE 32768
#define GSMEM  (2 * GSTAGE)

struct ChunkRegs {
    float2 a[2][4];      // [kf][quad]  A gmem data for this thread's frag slot
    float2 b[2][2][2];   // [j][kf][half] B gmem data
};

__global__ __launch_bounds__(256)
void gemm_mma(const float* __restrict__ A, const float* __restrict__ W,
              const float* __restrict__ bias, float* __restrict__ Cout,
              int M, int N, int K)
{
    extern __shared__ char smem[];
    const int tid = threadIdx.x;
    const int la  = tid & 31;
    const int wrp = tid >> 5;
    const int wm  = wrp >> 2;   // 0..1
    const int wn  = wrp & 3;    // 0..3
    const int brow = blockIdx.y * 128;
    const int bcol = blockIdx.x * 128;

    // Writer roles: warp wrp fills A frags mf=wrp (kf 0..1) and
    // B frags nf in {2*wrp, 2*wrp+1} (kf 0..1).
    const float* Ap = A + (size_t)(brow + wrp * 16 + (la >> 2)) * K + (la & 3) * 2;
    const float* Bp0 = W + (size_t)(bcol + (wrp * 2 + 0) * 8 + (la >> 2)) * K + (la & 3) * 2;
    const float* Bp1 = W + (size_t)(bcol + (wrp * 2 + 1) * 8 + (la >> 2)) * K + (la & 3) * 2;

    float acc[4][4][4];
#pragma unroll
    for (int i = 0; i < 4; i++)
#pragma unroll
        for (int j = 0; j < 4; j++)
#pragma unroll
            for (int r = 0; r < 4; r++) acc[i][j][r] = 0.f;

    auto ldg_chunk = [&](int kk, ChunkRegs& cr) {
#pragma unroll
        for (int kf = 0; kf < 2; kf++) {
            int k0 = kk + kf * 16;
            cr.a[kf][0] = *(const float2*)(Ap + k0);
            cr.a[kf][1] = *(const float2*)(Ap + 8 * K + k0);
            cr.a[kf][2] = *(const float2*)(Ap + k0 + 8);
            cr.a[kf][3] = *(const float2*)(Ap + 8 * K + k0 + 8);
            cr.b[0][kf][0] = *(const float2*)(Bp0 + k0);
            cr.b[0][kf][1] = *(const float2*)(Bp0 + k0 + 8);
            cr.b[1][kf][0] = *(const float2*)(Bp1 + k0);
            cr.b[1][kf][1] = *(const float2*)(Bp1 + k0 + 8);
        }
    };

    auto sts_chunk = [&](int stage, const ChunkRegs& cr) {
        char* base = smem + stage * GSTAGE;
#pragma unroll
        for (int kf = 0; kf < 2; kf++) {
            uint4 h, l;
            split2(cr.a[kf][0], h.x, l.x);
            split2(cr.a[kf][1], h.y, l.y);
            split2(cr.a[kf][2], h.z, l.z);
            split2(cr.a[kf][3], h.w, l.w);
            int foff = (wrp * 2 + kf) * 512 + la * 16;
            *(uint4*)(base + foff)        = h;
            *(uint4*)(base + 8192 + foff) = l;
#pragma unroll
            for (int j = 0; j < 2; j++) {
                uint2 bh, bl;
                split2(cr.b[j][kf][0], bh.x, bl.x);
                split2(cr.b[j][kf][1], bh.y, bl.y);
                int boff = ((wrp * 2 + j) * 2 + kf) * 256 + la * 8;
                *(uint2*)(base + 16384 + boff) = bh;
                *(uint2*)(base + 24576 + boff) = bl;
            }
        }
    };

    auto compute = [&](int stage) {
        char* base = smem + stage * GSTAGE;
#pragma unroll
        for (int kf = 0; kf < 2; kf++) {
            uint4 ah[4], al[4];
            uint2 bh[4], bl[4];
#pragma unroll
            for (int i = 0; i < 4; i++) {
                int foff = ((wm * 4 + i) * 2 + kf) * 512 + la * 16;
                ah[i] = *(const uint4*)(base + foff);
                al[i] = *(const uint4*)(base + 8192 + foff);
            }
#pragma unroll
            for (int j = 0; j < 4; j++) {
                int boff = ((wn * 4 + j) * 2 + kf) * 256 + la * 8;
                bh[j] = *(const uint2*)(base + 16384 + boff);
                bl[j] = *(const uint2*)(base + 24576 + boff);
            }
#pragma unroll
            for (int i = 0; i < 4; i++)
#pragma unroll
                for (int j = 0; j < 4; j++) {
                    mma16816(acc[i][j], ah[i], bh[j]);
                    mma16816(acc[i][j], ah[i], bl[j]);
                    mma16816(acc[i][j], al[i], bh[j]);
                }
        }
    };

    const int nch = K >> 5;   // K/32

    // Prologue: fill stage 0
    {
        ChunkRegs cr;
        ldg_chunk(0, cr);
        sts_chunk(0, cr);
    }
    __syncthreads();

    for (int c = 0; c < nch; c++) {
        ChunkRegs cr;
        bool more = (c + 1 < nch);
        if (more) ldg_chunk((c + 1) << 5, cr);
        compute(c & 1);
        if (more) sts_chunk((c + 1) & 1, cr);
        __syncthreads();
    }

    // Epilogue: registers -> gmem (+bias)
#pragma unroll
    for (int j = 0; j < 4; j++) {
        int c0 = bcol + wn * 32 + j * 8 + (la & 3) * 2;
        float bx = 0.f, by = 0.f;
        if (bias) { bx = bias[c0]; by = bias[c0 + 1]; }
#pragma unroll
        for (int i = 0; i < 4; i++) {
            int r0 = brow + wm * 64 + i * 16 + (la >> 2);
            float2 o0, o1;
            o0.x = acc[i][j][0] + bx; o0.y = acc[i][j][1] + by;
            o1.x = acc[i][j][2] + bx; o1.y = acc[i][j][3] + by;
            *(float2*)&Cout[(size_t)r0 * N + c0]       = o0;
            *(float2*)&Cout[(size_t)(r0 + 8) * N + c0] = o1;
        }
    }
}

// ---------------------------------------------------------------------------
// Flash attention (fp32, online softmax). One CTA per (b, h, 64-row q tile).
// (unchanged from round 1 — proven at 740us; mma conversion is next round)
// ---------------------------------------------------------------------------
#define ATTN_SMEM (4 * 64 * 65 * (int)sizeof(float))

__global__ __launch_bounds__(256)
void attn_kernel()
{
    const int qt = blockIdx.x;
    const int h  = blockIdx.y;
    const int b  = blockIdx.z;

    extern __shared__ float smemf[];
    float* sQ = smemf;
    float* sK = sQ + 64 * 65;
    float* sV = sK + 64 * 65;
    float* sP = sV + 64 * 65;

    const int tid = threadIdx.x;
    const int tx  = tid & 15;
    const int ty  = tid >> 4;
    const int r0  = ty * 4;
    const int c0  = tx * 4;
    const int qbase = qt * 64;

    const float* base = g_kqv + (size_t)b * TT * C3 + h * HD;
    const float* kptr = base;
    const float* qptr = base + NE;
    const float* vptr = base + 2 * NE;

    {
        const int t  = tid >> 4;
        const int d4 = (tid & 15) * 4;
#pragma unroll
        for (int it = 0; it < 4; it++) {
            int row = it * 16 + t;
            float4 v = *(const float4*)(qptr + (size_t)(qbase + row) * C3 + d4);
            sQ[(d4 + 0) * 65 + row] = v.x;
            sQ[(d4 + 1) * 65 + row] = v.y;
            sQ[(d4 + 2) * 65 + row] = v.z;
            sQ[(d4 + 3) * 65 + row] = v.w;
        }
    }

    float m_i[4], l_i[4], acc[4][4];
#pragma unroll
    for (int i = 0; i < 4; i++) {
        m_i[i] = -1e30f; l_i[i] = 0.f;
#pragma unroll
        for (int j = 0; j < 4; j++) acc[i][j] = 0.f;
    }

    const float scale = 0.125f;

    for (int kt = 0; kt <= qt; ++kt) {
        const int kbase = kt * 64;
        __syncthreads();

        {
            const int t  = tid >> 4;
            const int d4 = (tid & 15) * 4;
#pragma unroll
            for (int it = 0; it < 4; it++) {
                int row = it * 16 + t;
                float4 kv = *(const float4*)(kptr + (size_t)(kbase + row) * C3 + d4);
                sK[(d4 + 0) * 65 + row] = kv.x;
                sK[(d4 + 1) * 65 + row] = kv.y;
                sK[(d4 + 2) * 65 + row] = kv.z;
                sK[(d4 + 3) * 65 + row] = kv.w;
                float4 vv = *(const float4*)(vptr + (size_t)(kbase + row) * C3 + d4);
                sV[row * 65 + d4 + 0] = vv.x;
                sV[row * 65 + d4 + 1] = vv.y;
                sV[row * 65 + d4 + 2] = vv.z;
                sV[row * 65 + d4 + 3] = vv.w;
            }
        }
        __syncthreads();

        float s[4][4];
#pragma unroll
        for (int i = 0; i < 4; i++)
#pragma unroll
            for (int j = 0; j < 4; j++) s[i][j] = 0.f;

#pragma unroll 4
        for (int d = 0; d < 64; d++) {
            float rq[4], rk[4];
#pragma unroll
            for (int i = 0; i < 4; i++) rq[i] = sQ[d * 65 + r0 + i];
#pragma unroll
            for (int j = 0; j < 4; j++) rk[j] = sK[d * 65 + c0 + j];
#pragma unroll
            for (int i = 0; i < 4; i++)
#pragma unroll
                for (int j = 0; j < 4; j++)
                    s[i][j] = fmaf(rq[i], rk[j], s[i][j]);
        }

        if (kt == qt) {
#pragma unroll
            for (int i = 0; i < 4; i++)
#pragma unroll
                for (int j = 0; j < 4; j++)
                    s[i][j] = (c0 + j <= r0 + i) ? s[i][j] * scale : -1e30f;
        } else {
#pragma unroll
            for (int i = 0; i < 4; i++)
#pragma unroll
                for (int j = 0; j < 4; j++) s[i][j] *= scale;
        }

        float rmax[4];
#pragma unroll
        for (int i = 0; i < 4; i++)
            rmax[i] = fmaxf(fmaxf(s[i][0], s[i][1]), fmaxf(s[i][2], s[i][3]));
#pragma unroll
        for (int off = 8; off >= 1; off >>= 1) {
#pragma unroll
            for (int i = 0; i < 4; i++)
                rmax[i] = fmaxf(rmax[i], __shfl_xor_sync(0xffffffffu, rmax[i], off));
        }

        float mnew[4], alpha[4], rsum[4];
#pragma unroll
        for (int i = 0; i < 4; i++) {
            mnew[i]  = fmaxf(m_i[i], rmax[i]);
            alpha[i] = __expf(m_i[i] - mnew[i]);
            rsum[i]  = 0.f;
        }

        float p[4][4];
#pragma unroll
        for (int i = 0; i < 4; i++)
#pragma unroll
            for (int j = 0; j < 4; j++) {
                p[i][j] = __expf(s[i][j] - mnew[i]);
                rsum[i] += p[i][j];
            }
#pragma unroll
        for (int off = 8; off >= 1; off >>= 1) {
#pragma unroll
            for (int i = 0; i < 4; i++)
                rsum[i] += __shfl_xor_sync(0xffffffffu, rsum[i], off);
        }
#pragma unroll
        for (int i = 0; i < 4; i++) {
            l_i[i] = l_i[i] * alpha[i] + rsum[i];
            m_i[i] = mnew[i];
#pragma unroll
            for (int j = 0; j < 4; j++) acc[i][j] *= alpha[i];
        }

#pragma unroll
        for (int i = 0; i < 4; i++)
#pragma unroll
            for (int j = 0; j < 4; j++)
                sP[(c0 + j) * 65 + r0 + i] = p[i][j];
        __syncthreads();

#pragma unroll 4
        for (int c = 0; c < 64; c++) {
            float rp[4], rv[4];
#pragma unroll
            for (int i = 0; i < 4; i++) rp[i] = sP[c * 65 + r0 + i];
#pragma unroll
            for (int j = 0; j < 4; j++) rv[j] = sV[c * 65 + c0 + j];
#pragma unroll
            for (int i = 0; i < 4; i++)
#pragma unroll
                for (int j = 0; j < 4; j++)
                    acc[i][j] = fmaf(rp[i], rv[j], acc[i][j]);
        }
    }

#pragma unroll
    for (int i = 0; i < 4; i++) {
        float inv = 1.0f / l_i[i];
        float4 o;
        o.x = acc[i][0] * inv; o.y = acc[i][1] * inv;
        o.z = acc[i][2] * inv; o.w = acc[i][3] * inv;
        *(float4*)&g_attn[((size_t)b * TT + qbase + r0 + i) * NE + h * HD + c0] = o;
    }
}

// ---------------------------------------------------------------------------
// Launch
// ---------------------------------------------------------------------------
extern "C" void kernel_launch(void* const* d_in, const int* in_sizes, int n_in,
                              void* d_out, int out_size)
{
    const float* x = nullptr, *Wkqv = nullptr, *Wproj = nullptr, *bproj = nullptr;
    for (int i = 0; i < n_in; i++) {
        int sz = in_sizes[i];
        if      (sz == TB * TT * NE)      x     = (const float*)d_in[i];
        else if (sz == 3 * NE * NE)       Wkqv  = (const float*)d_in[i];
        else if (sz == NE * NE)           Wproj = (const float*)d_in[i];
        else if (sz == NE)                bproj = (const float*)d_in[i];
    }
    float* out = (float*)d_out;

    float* kqv  = nullptr;
    float* attn = nullptr;
    cudaGetSymbolAddress((void**)&kqv,  g_kqv);
    cudaGetSymbolAddress((void**)&attn, g_attn);

    cudaFuncSetAttribute(gemm_mma,
                         cudaFuncAttributeMaxDynamicSharedMemorySize, GSMEM);
    cudaFuncSetAttribute(attn_kernel,
                         cudaFuncAttributeMaxDynamicSharedMemorySize, ATTN_SMEM);

    const int M = TB * TT;  // 4096

    // 1) KQV projection: [4096,1024] @ [3072,1024]^T -> [4096,3072]
    {
        dim3 grid(C3 / 128, M / 128);
        gemm_mma<<<grid, 256, GSMEM>>>(x, Wkqv, nullptr, kqv, M, C3, NE);
    }

    // 2) Causal flash attention
    {
        dim3 grid(TT / 64, NH, TB);
        attn_kernel<<<grid, 256, ATTN_SMEM>>>();
    }

    // 3) Output projection + bias: [4096,1024] @ [1024,1024]^T + b -> out
    {
        dim3 grid(NE / 128, M / 128);
        gemm_mma<<<grid, 256, GSMEM>>>(attn, Wproj, bproj, out, M, NE, NE);
    }
}

// round 4
// speedup vs baseline: 2.1499x; 1.6237x over previous
#include <cuda_runtime.h>
#include <cuda_bf16.h>
#include <math.h>
#include <stddef.h>
#include <stdint.h>

// Problem constants
#define TB 2
#define TT 2048
#define NE 1024
#define NH 16
#define HD 64
#define C3 (3 * NE)   // 3072

// Scratch (allocation-free rule: device globals)
__device__ float g_kqv[(size_t)TB * TT * C3];   // [B*T, 3C]  (k | q | v)
__device__ float g_attn[(size_t)TB * TT * NE];  // [B*T, C]   attention output

// ===========================================================================
// mma.sync m16n8k16 bf16 -> f32  (standard PTX, works at compute_103)
// ===========================================================================
static __device__ __forceinline__ void mma16816(float* d, const uint4& a, const uint2& b) {
    asm volatile(
        "mma.sync.aligned.m16n8k16.row.col.f32.bf16.bf16.f32 "
        "{%0,%1,%2,%3}, {%4,%5,%6,%7}, {%8,%9}, {%0,%1,%2,%3};"
        : "+f"(d[0]), "+f"(d[1]), "+f"(d[2]), "+f"(d[3])
        : "r"(a.x), "r"(a.y), "r"(a.z), "r"(a.w), "r"(b.x), "r"(b.y));
}

// fp32 pair -> packed bf16 hi + packed bf16 lo  (x = hi + lo)
static __device__ __forceinline__ void split2(float2 f, uint32_t& h, uint32_t& l) {
    __nv_bfloat162 hp = __floats2bfloat162_rn(f.x, f.y);
    float2 hf = __bfloat1622float2(hp);
    __nv_bfloat162 lp = __floats2bfloat162_rn(f.x - hf.x, f.y - hf.y);
    h = *reinterpret_cast<uint32_t*>(&hp);
    l = *reinterpret_cast<uint32_t*>(&lp);
}

// ===========================================================================
// GEMM-NT via mma.sync (unchanged from round 3 — proven 242 TF/s split-3)
// ===========================================================================
#define GSTAGE 32768
#define GSMEM  (2 * GSTAGE)

struct ChunkRegs {
    float2 a[2][4];
    float2 b[2][2][2];
};

__global__ __launch_bounds__(256)
void gemm_mma(const float* __restrict__ A, const float* __restrict__ W,
              const float* __restrict__ bias, float* __restrict__ Cout,
              int M, int N, int K)
{
    extern __shared__ char smem[];
    const int tid = threadIdx.x;
    const int la  = tid & 31;
    const int wrp = tid >> 5;
    const int wm  = wrp >> 2;
    const int wn  = wrp & 3;
    const int brow = blockIdx.y * 128;
    const int bcol = blockIdx.x * 128;

    const float* Ap  = A + (size_t)(brow + wrp * 16 + (la >> 2)) * K + (la & 3) * 2;
    const float* Bp0 = W + (size_t)(bcol + (wrp * 2 + 0) * 8 + (la >> 2)) * K + (la & 3) * 2;
    const float* Bp1 = W + (size_t)(bcol + (wrp * 2 + 1) * 8 + (la >> 2)) * K + (la & 3) * 2;

    float acc[4][4][4];
#pragma unroll
    for (int i = 0; i < 4; i++)
#pragma unroll
        for (int j = 0; j < 4; j++)
#pragma unroll
            for (int r = 0; r < 4; r++) acc[i][j][r] = 0.f;

    auto ldg_chunk = [&](int kk, ChunkRegs& cr) {
#pragma unroll
        for (int kf = 0; kf < 2; kf++) {
            int k0 = kk + kf * 16;
            cr.a[kf][0] = *(const float2*)(Ap + k0);
            cr.a[kf][1] = *(const float2*)(Ap + 8 * K + k0);
            cr.a[kf][2] = *(const float2*)(Ap + k0 + 8);
            cr.a[kf][3] = *(const float2*)(Ap + 8 * K + k0 + 8);
            cr.b[0][kf][0] = *(const float2*)(Bp0 + k0);
            cr.b[0][kf][1] = *(const float2*)(Bp0 + k0 + 8);
            cr.b[1][kf][0] = *(const float2*)(Bp1 + k0);
            cr.b[1][kf][1] = *(const float2*)(Bp1 + k0 + 8);
        }
    };

    auto sts_chunk = [&](int stage, const ChunkRegs& cr) {
        char* base = smem + stage * GSTAGE;
#pragma unroll
        for (int kf = 0; kf < 2; kf++) {
            uint4 h, l;
            split2(cr.a[kf][0], h.x, l.x);
            split2(cr.a[kf][1], h.y, l.y);
            split2(cr.a[kf][2], h.z, l.z);
            split2(cr.a[kf][3], h.w, l.w);
            int foff = (wrp * 2 + kf) * 512 + la * 16;
            *(uint4*)(base + foff)        = h;
            *(uint4*)(base + 8192 + foff) = l;
#pragma unroll
            for (int j = 0; j < 2; j++) {
                uint2 bh, bl;
                split2(cr.b[j][kf][0], bh.x, bl.x);
                split2(cr.b[j][kf][1], bh.y, bl.y);
                int boff = ((wrp * 2 + j) * 2 + kf) * 256 + la * 8;
                *(uint2*)(base + 16384 + boff) = bh;
                *(uint2*)(base + 24576 + boff) = bl;
            }
        }
    };

    auto compute = [&](int stage) {
        char* base = smem + stage * GSTAGE;
#pragma unroll
        for (int kf = 0; kf < 2; kf++) {
            uint4 ah[4], al[4];
            uint2 bh[4], bl[4];
#pragma unroll
            for (int i = 0; i < 4; i++) {
                int foff = ((wm * 4 + i) * 2 + kf) * 512 + la * 16;
                ah[i] = *(const uint4*)(base + foff);
                al[i] = *(const uint4*)(base + 8192 + foff);
            }
#pragma unroll
            for (int j = 0; j < 4; j++) {
                int boff = ((wn * 4 + j) * 2 + kf) * 256 + la * 8;
                bh[j] = *(const uint2*)(base + 16384 + boff);
                bl[j] = *(const uint2*)(base + 24576 + boff);
            }
#pragma unroll
            for (int i = 0; i < 4; i++)
#pragma unroll
                for (int j = 0; j < 4; j++) {
                    mma16816(acc[i][j], ah[i], bh[j]);
                    mma16816(acc[i][j], ah[i], bl[j]);
                    mma16816(acc[i][j], al[i], bh[j]);
                }
        }
    };

    const int nch = K >> 5;

    {
        ChunkRegs cr;
        ldg_chunk(0, cr);
        sts_chunk(0, cr);
    }
    __syncthreads();

    for (int c = 0; c < nch; c++) {
        ChunkRegs cr;
        bool more = (c + 1 < nch);
        if (more) ldg_chunk((c + 1) << 5, cr);
        compute(c & 1);
        if (more) sts_chunk((c + 1) & 1, cr);
        __syncthreads();
    }

#pragma unroll
    for (int j = 0; j < 4; j++) {
        int c0 = bcol + wn * 32 + j * 8 + (la & 3) * 2;
        float bx = 0.f, by = 0.f;
        if (bias) { bx = bias[c0]; by = bias[c0 + 1]; }
#pragma unroll
        for (int i = 0; i < 4; i++) {
            int r0 = brow + wm * 64 + i * 16 + (la >> 2);
            float2 o0, o1;
            o0.x = acc[i][j][0] + bx; o0.y = acc[i][j][1] + by;
            o1.x = acc[i][j][2] + bx; o1.y = acc[i][j][3] + by;
            *(float2*)&Cout[(size_t)r0 * N + c0]       = o0;
            *(float2*)&Cout[(size_t)(r0 + 8) * N + c0] = o1;
        }
    }
}

// ===========================================================================
// Flash attention via mma.sync, bf16 split-3 both matmuls, f32 accumulate.
// One CTA per (b, h, 128 q-rows); 8 warps x 16 q-rows; K/V tiles of 64 keys.
//
// Smem per tile (single-buffered, 3 syncs/tile):
//   KH [0, 8K)     : K hi B-frags  (n=key 8nf, k=d 4kf), 32 frags x 256B
//   KL [8K, 16K)   : K lo
//   VH [16K, 24K)  : V hi B-frags  (n=d 8nf, k=key 4kf)
//   VL [24K, 32K)  : V lo
//   VS [32K, ~49K) : V fp32 stage [64 keys][64 d], row stride 67 (conflict-free)
// ===========================================================================
#define ATTN_SMEM (32768 + 64 * 67 * 4)

__global__ __launch_bounds__(256)
void attn_mma()
{
    const int qt = 15 - blockIdx.x;   // heavy CTAs first
    const int h  = blockIdx.y;
    const int b  = blockIdx.z;

    extern __shared__ char smem[];
    char*  KH = smem;
    char*  KL = smem + 8192;
    char*  VH = smem + 16384;
    char*  VL = smem + 24576;
    float* VS = (float*)(smem + 32768);

    const int tid = threadIdx.x;
    const int la  = tid & 31;
    const int w   = tid >> 5;
    const int r_in  = la >> 2;          // 0..7
    const int cpair = (la & 3) * 2;     // 0,2,4,6
    const int qbase = qt * 128;
    const int row0  = qbase + w * 16 + r_in;
    const int row1  = row0 + 8;

    const float* kq = g_kqv + (size_t)b * TT * C3 + h * HD;   // k plane
    // q at +NE, v at +2*NE within the row

    // --- Q fragments (A operand), scale 1/8 folded in exactly ---
    uint4 Qh[4], Ql[4];
    {
        const float* q0 = kq + NE + (size_t)(qbase + w * 16 + r_in) * C3;
#pragma unroll
        for (int kf = 0; kf < 4; kf++) {
            int k0 = kf * 16 + cpair;
            float2 x0 = *(const float2*)(q0 + k0);
            float2 x1 = *(const float2*)(q0 + 8 * C3 + k0);
            float2 x2 = *(const float2*)(q0 + k0 + 8);
            float2 x3 = *(const float2*)(q0 + 8 * C3 + k0 + 8);
            x0.x *= 0.125f; x0.y *= 0.125f;
            x1.x *= 0.125f; x1.y *= 0.125f;
            x2.x *= 0.125f; x2.y *= 0.125f;
            x3.x *= 0.125f; x3.y *= 0.125f;
            split2(x0, Qh[kf].x, Ql[kf].x);
            split2(x1, Qh[kf].y, Ql[kf].y);
            split2(x2, Qh[kf].z, Ql[kf].z);
            split2(x3, Qh[kf].w, Ql[kf].w);
        }
    }

    float o[8][4];
#pragma unroll
    for (int nf = 0; nf < 8; nf++)
#pragma unroll
        for (int r = 0; r < 4; r++) o[nf][r] = 0.f;
    float m0 = -1e30f, m1 = -1e30f, l0 = 0.f, l1 = 0.f;

    const int ntiles = 2 * qt + 2;
    const float* vsrc = kq + 2 * NE;

    for (int kt = 0; kt < ntiles; kt++) {
        const int kbase = kt * 64;
        __syncthreads();   // frag buffers free

        // --- fill K frags (direct from gmem) + V fp32 stage ---
#pragma unroll
        for (int i = 0; i < 4; i++) {
            int s = tid + (i << 8);
            int f = s >> 5, ln = s & 31;
            int nf = f >> 2, kf = f & 3;
            int key = nf * 8 + (ln >> 2);
            int d0  = kf * 16 + (ln & 3) * 2;
            const float* src = kq + (size_t)(kbase + key) * C3 + d0;
            float2 a = *(const float2*)src;
            float2 c = *(const float2*)(src + 8);
            uint2 hh, ll;
            split2(a, hh.x, ll.x);
            split2(c, hh.y, ll.y);
            int off = f * 256 + ln * 8;
            *(uint2*)(KH + off) = hh;
            *(uint2*)(KL + off) = ll;
        }
#pragma unroll
        for (int i = 0; i < 4; i++) {
            int s = tid + (i << 8);
            int key = s >> 4, d4 = (s & 15) * 4;
            float4 v = *(const float4*)(vsrc + (size_t)(kbase + key) * C3 + d4);
            float* dst = VS + key * 67 + d4;
            dst[0] = v.x; dst[1] = v.y; dst[2] = v.z; dst[3] = v.w;
        }
        __syncthreads();

        // --- build V frags from stage (transpose: n=d, k=key) ---
#pragma unroll
        for (int i = 0; i < 4; i++) {
            int s = tid + (i << 8);
            int f = s >> 5, ln = s & 31;
            int nf = f >> 2, kf = f & 3;
            int d  = nf * 8 + (ln >> 2);
            int k0 = kf * 16 + (ln & 3) * 2;
            float2 a = make_float2(VS[k0 * 67 + d],       VS[(k0 + 1) * 67 + d]);
            float2 c = make_float2(VS[(k0 + 8) * 67 + d], VS[(k0 + 9) * 67 + d]);
            uint2 hh, ll;
            split2(a, hh.x, ll.x);
            split2(c, hh.y, ll.y);
            int off = f * 256 + ln * 8;
            *(uint2*)(VH + off) = hh;
            *(uint2*)(VL + off) = ll;
        }
        __syncthreads();

        // --- S = (Q/8) K^T  (split-3) ---
        float sfr[8][4];
#pragma unroll
        for (int nf = 0; nf < 8; nf++)
#pragma unroll
            for (int r = 0; r < 4; r++) sfr[nf][r] = 0.f;

#pragma unroll
        for (int kf = 0; kf < 4; kf++) {
#pragma unroll
            for (int nf = 0; nf < 8; nf++) {
                int off = (nf * 4 + kf) * 256 + la * 8;
                uint2 kh = *(const uint2*)(KH + off);
                uint2 kl = *(const uint2*)(KL + off);
                mma16816(sfr[nf], Qh[kf], kh);
                mma16816(sfr[nf], Qh[kf], kl);
                mma16816(sfr[nf], Ql[kf], kh);
            }
        }

        // --- causal mask (only near-diagonal tiles) ---
        if (kbase + 63 > qbase + w * 16) {
#pragma unroll
            for (int nf = 0; nf < 8; nf++) {
                int c = kbase + nf * 8 + cpair;
                if (c     > row0) sfr[nf][0] = -1e30f;
                if (c + 1 > row0) sfr[nf][1] = -1e30f;
                if (c     > row1) sfr[nf][2] = -1e30f;
                if (c + 1 > row1) sfr[nf][3] = -1e30f;
            }
        }

        // --- online softmax (rows r_in and r_in+8; quad shfl reduce) ---
        float mx0 = -1e30f, mx1 = -1e30f;
#pragma unroll
        for (int nf = 0; nf < 8; nf++) {
            mx0 = fmaxf(mx0, fmaxf(sfr[nf][0], sfr[nf][1]));
            mx1 = fmaxf(mx1, fmaxf(sfr[nf][2], sfr[nf][3]));
        }
        mx0 = fmaxf(mx0, __shfl_xor_sync(0xffffffffu, mx0, 1));
        mx0 = fmaxf(mx0, __shfl_xor_sync(0xffffffffu, mx0, 2));
        mx1 = fmaxf(mx1, __shfl_xor_sync(0xffffffffu, mx1, 1));
        mx1 = fmaxf(mx1, __shfl_xor_sync(0xffffffffu, mx1, 2));

        float mn0 = fmaxf(m0, mx0), mn1 = fmaxf(m1, mx1);
        float a0 = __expf(m0 - mn0), a1 = __expf(m1 - mn1);
        float s0 = 0.f, s1 = 0.f;
#pragma unroll
        for (int nf = 0; nf < 8; nf++) {
            sfr[nf][0] = __expf(sfr[nf][0] - mn0);
            sfr[nf][1] = __expf(sfr[nf][1] - mn0);
            sfr[nf][2] = __expf(sfr[nf][2] - mn1);
            sfr[nf][3] = __expf(sfr[nf][3] - mn1);
            s0 += sfr[nf][0] + sfr[nf][1];
            s1 += sfr[nf][2] + sfr[nf][3];
        }
        s0 += __shfl_xor_sync(0xffffffffu, s0, 1);
        s0 += __shfl_xor_sync(0xffffffffu, s0, 2);
        s1 += __shfl_xor_sync(0xffffffffu, s1, 1);
        s1 += __shfl_xor_sync(0xffffffffu, s1, 2);

        l0 = l0 * a0 + s0;  l1 = l1 * a1 + s1;
        m0 = mn0;           m1 = mn1;
#pragma unroll
        for (int nf = 0; nf < 8; nf++) {
            o[nf][0] *= a0; o[nf][1] *= a0;
            o[nf][2] *= a1; o[nf][3] *= a1;
        }

        // --- O += P V  (P frags built by register retag; split-3) ---
#pragma unroll
        for (int kf2 = 0; kf2 < 4; kf2++) {
            uint4 Ph, Pl;
            split2(make_float2(sfr[2 * kf2][0],     sfr[2 * kf2][1]),     Ph.x, Pl.x);
            split2(make_float2(sfr[2 * kf2][2],     sfr[2 * kf2][3]),     Ph.y, Pl.y);
            split2(make_float2(sfr[2 * kf2 + 1][0], sfr[2 * kf2 + 1][1]), Ph.z, Pl.z);
            split2(make_float2(sfr[2 * kf2 + 1][2], sfr[2 * kf2 + 1][3]), Ph.w, Pl.w);
#pragma unroll
            for (int nf = 0; nf < 8; nf++) {
                int off = (nf * 4 + kf2) * 256 + la * 8;
                uint2 vh = *(const uint2*)(VH + off);
                uint2 vl = *(const uint2*)(VL + off);
                mma16816(o[nf], Ph, vh);
                mma16816(o[nf], Ph, vl);
                mma16816(o[nf], Pl, vh);
            }
        }
    }

    // --- epilogue: O / l -> g_attn[b, row, h*64 + d] ---
    float i0 = 1.f / l0, i1 = 1.f / l1;
    float* dst0 = g_attn + (size_t)(b * TT + row0) * NE + h * HD + cpair;
    float* dst1 = dst0 + 8 * NE;
#pragma unroll
    for (int nf = 0; nf < 8; nf++) {
        float2 v0, v1;
        v0.x = o[nf][0] * i0; v0.y = o[nf][1] * i0;
        v1.x = o[nf][2] * i1; v1.y = o[nf][3] * i1;
        *(float2*)(dst0 + nf * 8) = v0;
        *(float2*)(dst1 + nf * 8) = v1;
    }
}

// ---------------------------------------------------------------------------
// Launch
// ---------------------------------------------------------------------------
extern "C" void kernel_launch(void* const* d_in, const int* in_sizes, int n_in,
                              void* d_out, int out_size)
{
    const float* x = nullptr, *Wkqv = nullptr, *Wproj = nullptr, *bproj = nullptr;
    for (int i = 0; i < n_in; i++) {
        int sz = in_sizes[i];
        if      (sz == TB * TT * NE)      x     = (const float*)d_in[i];
        else if (sz == 3 * NE * NE)       Wkqv  = (const float*)d_in[i];
        else if (sz == NE * NE)           Wproj = (const float*)d_in[i];
        else if (sz == NE)                bproj = (const float*)d_in[i];
    }
    float* out = (float*)d_out;

    float* kqv  = nullptr;
    float* attn = nullptr;
    cudaGetSymbolAddress((void**)&kqv,  g_kqv);
    cudaGetSymbolAddress((void**)&attn, g_attn);

    cudaFuncSetAttribute(gemm_mma,
                         cudaFuncAttributeMaxDynamicSharedMemorySize, GSMEM);
    cudaFuncSetAttribute(attn_mma,
                         cudaFuncAttributeMaxDynamicSharedMemorySize, ATTN_SMEM);

    const int M = TB * TT;  // 4096

    // 1) KQV projection: [4096,1024] @ [3072,1024]^T -> [4096,3072]
    {
        dim3 grid(C3 / 128, M / 128);
        gemm_mma<<<grid, 256, GSMEM>>>(x, Wkqv, nullptr, kqv, M, C3, NE);
    }

    // 2) Causal flash attention (mma.sync)
    {
        dim3 grid(TT / 128, NH, TB);
        attn_mma<<<grid, 256, ATTN_SMEM>>>();
    }

    // 3) Output projection + bias: [4096,1024] @ [1024,1024]^T + b -> out
    {
        dim3 grid(NE / 128, M / 128);
        gemm_mma<<<grid, 256, GSMEM>>>(attn, Wproj, bproj, out, M, NE, NE);
    }
}

// round 5
// speedup vs baseline: 2.6955x; 1.2538x over previous
#include <cuda_runtime.h>
#include <cuda_bf16.h>
#include <math.h>
#include <stddef.h>
#include <stdint.h>

// Problem constants
#define TB 2
#define TT 2048
#define NE 1024
#define NH 16
#define HD 64
#define C3 (3 * NE)   // 3072

// Scratch (allocation-free rule: device globals)
__device__ float g_kqv[(size_t)TB * TT * C3];   // [B*T, 3C]  (k | q | v)
__device__ float g_attn[(size_t)TB * TT * NE];  // [B*T, C]

// Fragment-major bf16 hi/lo planes (mma register layout in gmem).
// A-frag plane (16x16 tile): [R/16][64][32] uint4.  (K fixed = 1024, nfk = 64)
// B-frag plane (8x16 tile):  [N/8 ][64][32] uint2.
__device__ uint4 g_xAh [(size_t)256 * 64 * 32];   // x      4096x1024
__device__ uint4 g_xAl [(size_t)256 * 64 * 32];
__device__ uint4 g_atAh[(size_t)256 * 64 * 32];   // attn   4096x1024
__device__ uint4 g_atAl[(size_t)256 * 64 * 32];
__device__ uint2 g_WkBh[(size_t)384 * 64 * 32];   // W_kqv  3072x1024
__device__ uint2 g_WkBl[(size_t)384 * 64 * 32];
__device__ uint2 g_WpBh[(size_t)128 * 64 * 32];   // W_proj 1024x1024
__device__ uint2 g_WpBl[(size_t)128 * 64 * 32];

// ===========================================================================
// PTX helpers
// ===========================================================================
static __device__ __forceinline__ void mma16816(float* d, const uint4& a, const uint2& b) {
    asm volatile(
        "mma.sync.aligned.m16n8k16.row.col.f32.bf16.bf16.f32 "
        "{%0,%1,%2,%3}, {%4,%5,%6,%7}, {%8,%9}, {%0,%1,%2,%3};"
        : "+f"(d[0]), "+f"(d[1]), "+f"(d[2]), "+f"(d[3])
        : "r"(a.x), "r"(a.y), "r"(a.z), "r"(a.w), "r"(b.x), "r"(b.y));
}

static __device__ __forceinline__ void split2(float2 f, uint32_t& h, uint32_t& l) {
    __nv_bfloat162 hp = __floats2bfloat162_rn(f.x, f.y);
    float2 hf = __bfloat1622float2(hp);
    __nv_bfloat162 lp = __floats2bfloat162_rn(f.x - hf.x, f.y - hf.y);
    h = *reinterpret_cast<uint32_t*>(&hp);
    l = *reinterpret_cast<uint32_t*>(&lp);
}

static __device__ __forceinline__ uint32_t smem_u32(const void* p) {
    uint32_t a;
    asm("{ .reg .u64 t; cvta.to.shared.u64 t, %1; cvt.u32.u64 %0, t; }"
        : "=r"(a) : "l"(p));
    return a;
}

#define CP16(dst, src) \
    asm volatile("cp.async.cg.shared.global [%0], [%1], 16;" :: "r"(dst), "l"(src))
#define CP_COMMIT() asm volatile("cp.async.commit_group;" ::: "memory")
#define CP_WAIT1()  asm volatile("cp.async.wait_group 1;" ::: "memory")
#define CP_WAIT0()  asm volatile("cp.async.wait_group 0;" ::: "memory")

// ===========================================================================
// Prep kernels: fp32 row-major -> fragment-major bf16 hi/lo planes (K = 1024)
// ===========================================================================
__global__ __launch_bounds__(256)
void prep_a(const float* __restrict__ src, uint4* __restrict__ hi, uint4* __restrict__ lo)
{
    int slot = blockIdx.x * 256 + threadIdx.x;   // [R/16 * 64][32]
    int frag = slot >> 5, la = slot & 31;
    int row = ((frag >> 6) << 4) + (la >> 2);
    int k   = ((frag & 63) << 4) + ((la & 3) << 1);
    const float* p = src + (size_t)row * 1024 + k;
    float2 x0 = *(const float2*)p;
    float2 x1 = *(const float2*)(p + 8 * 1024);
    float2 x2 = *(const float2*)(p + 8);
    float2 x3 = *(const float2*)(p + 8 * 1024 + 8);
    uint4 h, l;
    split2(x0, h.x, l.x);
    split2(x1, h.y, l.y);
    split2(x2, h.z, l.z);
    split2(x3, h.w, l.w);
    hi[slot] = h;
    lo[slot] = l;
}

__global__ __launch_bounds__(256)
void prep_b(const float* __restrict__ src, uint2* __restrict__ hi, uint2* __restrict__ lo)
{
    int slot = blockIdx.x * 256 + threadIdx.x;   // [N/8 * 64][32]
    int frag = slot >> 5, la = slot & 31;
    int n = ((frag >> 6) << 3) + (la >> 2);
    int k = ((frag & 63) << 4) + ((la & 3) << 1);
    const float* p = src + (size_t)n * 1024 + k;
    float2 x0 = *(const float2*)p;
    float2 x1 = *(const float2*)(p + 8);
    uint2 h, l;
    split2(x0, h.x, l.x);
    split2(x1, h.y, l.y);
    hi[slot] = h;
    lo[slot] = l;
}

// ===========================================================================
// GEMM via mma.sync from pre-split fragment-major bf16 (K = 1024).
// CTA 128x128, chunk = 32 K-elems (2 kf frags), cp.async double buffer.
// smem stage 32KB: Ah[16 frag x512] Al Bh[32 frag x256] Bl.  2 stages = 64KB.
// 8 warps (2M x 4N), warp tile 64x32, split-3 MMA.
// ===========================================================================
#define GSTAGE 32768
#define GSMEM  (2 * GSTAGE)

__global__ __launch_bounds__(256, 2)
void gemm_bf(const uint4* __restrict__ Ah, const uint4* __restrict__ Al,
             const uint2* __restrict__ Bh, const uint2* __restrict__ Bl,
             const float* __restrict__ bias, float* __restrict__ Cout, int N)
{
    extern __shared__ char smem[];
    const uint32_t sb = smem_u32(smem);
    const int tid = threadIdx.x;
    const int la  = tid & 31;
    const int wrp = tid >> 5;
    const int wm  = wrp >> 2;
    const int wn  = wrp & 3;
    const int r16b = blockIdx.y * 8;    // A frag-row base
    const int n8b  = blockIdx.x * 16;   // B frag-row base

    float acc[4][4][4];
#pragma unroll
    for (int i = 0; i < 4; i++)
#pragma unroll
        for (int j = 0; j < 4; j++)
#pragma unroll
            for (int r = 0; r < 4; r++) acc[i][j][r] = 0.f;

    auto issue = [&](int stage, int kc) {
        uint32_t base = sb + stage * GSTAGE;
        // A planes: 16 frags x 32 units(16B) each = 512 units/plane
#pragma unroll
        for (int rep = 0; rep < 2; rep++) {
            int u = rep * 256 + tid;
            int f = u >> 5, ln = u & 31;
            int ga = ((r16b + (f >> 1)) << 6) + (kc << 1) + (f & 1);
            CP16(base + f * 512 + ln * 16,        Ah + (size_t)ga * 32 + ln);
            CP16(base + 8192 + f * 512 + ln * 16, Al + (size_t)ga * 32 + ln);
        }
        // B planes: 32 frags x 16 units each = 512 units/plane
#pragma unroll
        for (int rep = 0; rep < 2; rep++) {
            int u = rep * 256 + tid;
            int f = u >> 4, j = u & 15;
            int gb = ((n8b + (f >> 1)) << 6) + (kc << 1) + (f & 1);
            CP16(base + 16384 + f * 256 + j * 16,
                 (const uint4*)Bh + (size_t)gb * 16 + j);
            CP16(base + 24576 + f * 256 + j * 16,
                 (const uint4*)Bl + (size_t)gb * 16 + j);
        }
        CP_COMMIT();
    };

    auto compute = [&](int stage) {
        char* base = smem + stage * GSTAGE;
#pragma unroll
        for (int kf = 0; kf < 2; kf++) {
            uint4 ah[4], al[4];
            uint2 bh[4], bl[4];
#pragma unroll
            for (int i = 0; i < 4; i++) {
                int foff = ((wm * 4 + i) * 2 + kf) * 512 + la * 16;
                ah[i] = *(const uint4*)(base + foff);
                al[i] = *(const uint4*)(base + 8192 + foff);
            }
#pragma unroll
            for (int j = 0; j < 4; j++) {
                int boff = ((wn * 4 + j) * 2 + kf) * 256 + la * 8;
                bh[j] = *(const uint2*)(base + 16384 + boff);
                bl[j] = *(const uint2*)(base + 24576 + boff);
            }
#pragma unroll
            for (int i = 0; i < 4; i++)
#pragma unroll
                for (int j = 0; j < 4; j++) {
                    mma16816(acc[i][j], ah[i], bh[j]);
                    mma16816(acc[i][j], ah[i], bl[j]);
                    mma16816(acc[i][j], al[i], bh[j]);
                }
        }
    };

    issue(0, 0);

    for (int kc = 0; kc < 32; kc++) {
        if (kc < 31) {
            issue((kc + 1) & 1, kc + 1);
            CP_WAIT1();
        } else {
            CP_WAIT0();
        }
        __syncthreads();
        compute(kc & 1);
        __syncthreads();
    }

    // Epilogue: registers -> gmem (+bias)
    const int brow = blockIdx.y * 128;
    const int bcol = blockIdx.x * 128;
#pragma unroll
    for (int j = 0; j < 4; j++) {
        int c0 = bcol + wn * 32 + j * 8 + (la & 3) * 2;
        float bx = 0.f, by = 0.f;
        if (bias) { bx = bias[c0]; by = bias[c0 + 1]; }
#pragma unroll
        for (int i = 0; i < 4; i++) {
            int r0 = brow + wm * 64 + i * 16 + (la >> 2);
            float2 o0, o1;
            o0.x = acc[i][j][0] + bx; o0.y = acc[i][j][1] + by;
            o1.x = acc[i][j][2] + bx; o1.y = acc[i][j][3] + by;
            *(float2*)&Cout[(size_t)r0 * N + c0]       = o0;
            *(float2*)&Cout[(size_t)(r0 + 8) * N + c0] = o1;
        }
    }
}

// ===========================================================================
// Flash attention via mma.sync (unchanged from round 4 — passed at ~300us)
// ===========================================================================
#define ATTN_SMEM (32768 + 64 * 67 * 4)

__global__ __launch_bounds__(256)
void attn_mma()
{
    const int qt = 15 - blockIdx.x;
    const int h  = blockIdx.y;
    const int b  = blockIdx.z;

    extern __shared__ char smem[];
    char*  KH = smem;
    char*  KL = smem + 8192;
    char*  VH = smem + 16384;
    char*  VL = smem + 24576;
    float* VS = (float*)(smem + 32768);

    const int tid = threadIdx.x;
    const int la  = tid & 31;
    const int w   = tid >> 5;
    const int r_in  = la >> 2;
    const int cpair = (la & 3) * 2;
    const int qbase = qt * 128;
    const int row0  = qbase + w * 16 + r_in;
    const int row1  = row0 + 8;

    const float* kq = g_kqv + (size_t)b * TT * C3 + h * HD;

    uint4 Qh[4], Ql[4];
    {
        const float* q0 = kq + NE + (size_t)(qbase + w * 16 + r_in) * C3;
#pragma unroll
        for (int kf = 0; kf < 4; kf++) {
            int k0 = kf * 16 + cpair;
            float2 x0 = *(const float2*)(q0 + k0);
            float2 x1 = *(const float2*)(q0 + 8 * C3 + k0);
            float2 x2 = *(const float2*)(q0 + k0 + 8);
            float2 x3 = *(const float2*)(q0 + 8 * C3 + k0 + 8);
            x0.x *= 0.125f; x0.y *= 0.125f;
            x1.x *= 0.125f; x1.y *= 0.125f;
            x2.x *= 0.125f; x2.y *= 0.125f;
            x3.x *= 0.125f; x3.y *= 0.125f;
            split2(x0, Qh[kf].x, Ql[kf].x);
            split2(x1, Qh[kf].y, Ql[kf].y);
            split2(x2, Qh[kf].z, Ql[kf].z);
            split2(x3, Qh[kf].w, Ql[kf].w);
        }
    }

    float o[8][4];
#pragma unroll
    for (int nf = 0; nf < 8; nf++)
#pragma unroll
        for (int r = 0; r < 4; r++) o[nf][r] = 0.f;
    float m0 = -1e30f, m1 = -1e30f, l0 = 0.f, l1 = 0.f;

    const int ntiles = 2 * qt + 2;
    const float* vsrc = kq + 2 * NE;

    for (int kt = 0; kt < ntiles; kt++) {
        const int kbase = kt * 64;
        __syncthreads();

#pragma unroll
        for (int i = 0; i < 4; i++) {
            int s = tid + (i << 8);
            int f = s >> 5, ln = s & 31;
            int nf = f >> 2, kf = f & 3;
            int key = nf * 8 + (ln >> 2);
            int d0  = kf * 16 + (ln & 3) * 2;
            const float* src = kq + (size_t)(kbase + key) * C3 + d0;
            float2 a = *(const float2*)src;
            float2 c = *(const float2*)(src + 8);
            uint2 hh, ll;
            split2(a, hh.x, ll.x);
            split2(c, hh.y, ll.y);
            int off = f * 256 + ln * 8;
            *(uint2*)(KH + off) = hh;
            *(uint2*)(KL + off) = ll;
        }
#pragma unroll
        for (int i = 0; i < 4; i++) {
            int s = tid + (i << 8);
            int key = s >> 4, d4 = (s & 15) * 4;
            float4 v = *(const float4*)(vsrc + (size_t)(kbase + key) * C3 + d4);
            float* dst = VS + key * 67 + d4;
            dst[0] = v.x; dst[1] = v.y; dst[2] = v.z; dst[3] = v.w;
        }
        __syncthreads();

#pragma unroll
        for (int i = 0; i < 4; i++) {
            int s = tid + (i << 8);
            int f = s >> 5, ln = s & 31;
            int nf = f >> 2, kf = f & 3;
            int d  = nf * 8 + (ln >> 2);
            int k0 = kf * 16 + (ln & 3) * 2;
            float2 a = make_float2(VS[k0 * 67 + d],       VS[(k0 + 1) * 67 + d]);
            float2 c = make_float2(VS[(k0 + 8) * 67 + d], VS[(k0 + 9) * 67 + d]);
            uint2 hh, ll;
            split2(a, hh.x, ll.x);
            split2(c, hh.y, ll.y);
            int off = f * 256 + ln * 8;
            *(uint2*)(VH + off) = hh;
            *(uint2*)(VL + off) = ll;
        }
        __syncthreads();

        float sfr[8][4];
#pragma unroll
        for (int nf = 0; nf < 8; nf++)
#pragma unroll
            for (int r = 0; r < 4; r++) sfr[nf][r] = 0.f;

#pragma unroll
        for (int kf = 0; kf < 4; kf++) {
#pragma unroll
            for (int nf = 0; nf < 8; nf++) {
                int off = (nf * 4 + kf) * 256 + la * 8;
                uint2 kh = *(const uint2*)(KH + off);
                uint2 kl = *(const uint2*)(KL + off);
                mma16816(sfr[nf], Qh[kf], kh);
                mma16816(sfr[nf], Qh[kf], kl);
                mma16816(sfr[nf], Ql[kf], kh);
            }
        }

        if (kbase + 63 > qbase + w * 16) {
#pragma unroll
            for (int nf = 0; nf < 8; nf++) {
                int c = kbase + nf * 8 + cpair;
                if (c     > row0) sfr[nf][0] = -1e30f;
                if (c + 1 > row0) sfr[nf][1] = -1e30f;
                if (c     > row1) sfr[nf][2] = -1e30f;
                if (c + 1 > row1) sfr[nf][3] = -1e30f;
            }
        }

        float mx0 = -1e30f, mx1 = -1e30f;
#pragma unroll
        for (int nf = 0; nf < 8; nf++) {
            mx0 = fmaxf(mx0, fmaxf(sfr[nf][0], sfr[nf][1]));
            mx1 = fmaxf(mx1, fmaxf(sfr[nf][2], sfr[nf][3]));
        }
        mx0 = fmaxf(mx0, __shfl_xor_sync(0xffffffffu, mx0, 1));
        mx0 = fmaxf(mx0, __shfl_xor_sync(0xffffffffu, mx0, 2));
        mx1 = fmaxf(mx1, __shfl_xor_sync(0xffffffffu, mx1, 1));
        mx1 = fmaxf(mx1, __shfl_xor_sync(0xffffffffu, mx1, 2));

        float mn0 = fmaxf(m0, mx0), mn1 = fmaxf(m1, mx1);
        float a0 = __expf(m0 - mn0), a1 = __expf(m1 - mn1);
        float s0 = 0.f, s1 = 0.f;
#pragma unroll
        for (int nf = 0; nf < 8; nf++) {
            sfr[nf][0] = __expf(sfr[nf][0] - mn0);
            sfr[nf][1] = __expf(sfr[nf][1] - mn0);
            sfr[nf][2] = __expf(sfr[nf][2] - mn1);
            sfr[nf][3] = __expf(sfr[nf][3] - mn1);
            s0 += sfr[nf][0] + sfr[nf][1];
            s1 += sfr[nf][2] + sfr[nf][3];
        }
        s0 += __shfl_xor_sync(0xffffffffu, s0, 1);
        s0 += __shfl_xor_sync(0xffffffffu, s0, 2);
        s1 += __shfl_xor_sync(0xffffffffu, s1, 1);
        s1 += __shfl_xor_sync(0xffffffffu, s1, 2);

        l0 = l0 * a0 + s0;  l1 = l1 * a1 + s1;
        m0 = mn0;           m1 = mn1;
#pragma unroll
        for (int nf = 0; nf < 8; nf++) {
            o[nf][0] *= a0; o[nf][1] *= a0;
            o[nf][2] *= a1; o[nf][3] *= a1;
        }

#pragma unroll
        for (int kf2 = 0; kf2 < 4; kf2++) {
            uint4 Ph, Pl;
            split2(make_float2(sfr[2 * kf2][0],     sfr[2 * kf2][1]),     Ph.x, Pl.x);
            split2(make_float2(sfr[2 * kf2][2],     sfr[2 * kf2][3]),     Ph.y, Pl.y);
            split2(make_float2(sfr[2 * kf2 + 1][0], sfr[2 * kf2 + 1][1]), Ph.z, Pl.z);
            split2(make_float2(sfr[2 * kf2 + 1][2], sfr[2 * kf2 + 1][3]), Ph.w, Pl.w);
#pragma unroll
            for (int nf = 0; nf < 8; nf++) {
                int off = (nf * 4 + kf2) * 256 + la * 8;
                uint2 vh = *(const uint2*)(VH + off);
                uint2 vl = *(const uint2*)(VL + off);
                mma16816(o[nf], Ph, vh);
                mma16816(o[nf], Ph, vl);
                mma16816(o[nf], Pl, vh);
            }
        }
    }

    float i0 = 1.f / l0, i1 = 1.f / l1;
    float* dst0 = g_attn + (size_t)(b * TT + row0) * NE + h * HD + cpair;
    float* dst1 = dst0 + 8 * NE;
#pragma unroll
    for (int nf = 0; nf < 8; nf++) {
        float2 v0, v1;
        v0.x = o[nf][0] * i0; v0.y = o[nf][1] * i0;
        v1.x = o[nf][2] * i1; v1.y = o[nf][3] * i1;
        *(float2*)(dst0 + nf * 8) = v0;
        *(float2*)(dst1 + nf * 8) = v1;
    }
}

// ---------------------------------------------------------------------------
// Launch
// ---------------------------------------------------------------------------
extern "C" void kernel_launch(void* const* d_in, const int* in_sizes, int n_in,
                              void* d_out, int out_size)
{
    const float* x = nullptr, *Wkqv = nullptr, *Wproj = nullptr, *bproj = nullptr;
    for (int i = 0; i < n_in; i++) {
        int sz = in_sizes[i];
        if      (sz == TB * TT * NE)      x     = (const float*)d_in[i];
        else if (sz == 3 * NE * NE)       Wkqv  = (const float*)d_in[i];
        else if (sz == NE * NE)           Wproj = (const float*)d_in[i];
        else if (sz == NE)                bproj = (const float*)d_in[i];
    }
    float* out = (float*)d_out;

    float *kqv, *attn;
    uint4 *xAh, *xAl, *atAh, *atAl;
    uint2 *WkBh, *WkBl, *WpBh, *WpBl;
    cudaGetSymbolAddress((void**)&kqv,  g_kqv);
    cudaGetSymbolAddress((void**)&attn, g_attn);
    cudaGetSymbolAddress((void**)&xAh,  g_xAh);
    cudaGetSymbolAddress((void**)&xAl,  g_xAl);
    cudaGetSymbolAddress((void**)&atAh, g_atAh);
    cudaGetSymbolAddress((void**)&atAl, g_atAl);
    cudaGetSymbolAddress((void**)&WkBh, g_WkBh);
    cudaGetSymbolAddress((void**)&WkBl, g_WkBl);
    cudaGetSymbolAddress((void**)&WpBh, g_WpBh);
    cudaGetSymbolAddress((void**)&WpBl, g_WpBl);

    cudaFuncSetAttribute(gemm_bf,
                         cudaFuncAttributeMaxDynamicSharedMemorySize, GSMEM);
    cudaFuncSetAttribute(attn_mma,
                         cudaFuncAttributeMaxDynamicSharedMemorySize, ATTN_SMEM);

    // Prep: fragment-major bf16 hi/lo
    prep_a<<<2048, 256>>>(x, xAh, xAl);               // 4096x1024
    prep_b<<<3072, 256>>>(Wkqv, WkBh, WkBl);          // 3072x1024
    prep_b<<<1024, 256>>>(Wproj, WpBh, WpBl);         // 1024x1024

    // 1) KQV projection -> g_kqv (fp32)
    {
        dim3 grid(C3 / 128, 32);
        gemm_bf<<<grid, 256, GSMEM>>>(xAh, xAl, WkBh, WkBl, nullptr, kqv, C3);
    }

    // 2) Causal flash attention -> g_attn (fp32)
    {
        dim3 grid(TT / 128, NH, TB);
        attn_mma<<<grid, 256, ATTN_SMEM>>>();
    }

    // 3) attn -> fragment-major, then output projection + bias
    prep_a<<<2048, 256>>>(attn, atAh, atAl);
    {
        dim3 grid(NE / 128, 32);
        gemm_bf<<<grid, 256, GSMEM>>>(atAh, atAl, WpBh, WpBl, bproj, out, NE);
    }
}

// round 6
// speedup vs baseline: 3.1901x; 1.1835x over previous
#include <cuda_runtime.h>
#include <cuda_bf16.h>
#include <math.h>
#include <stddef.h>
#include <stdint.h>

// Problem constants
#define TB 2
#define TT 2048
#define NE 1024
#define NH 16
#define HD 64
#define C3 (3 * NE)   // 3072

// Scratch (allocation-free rule: device globals)
__device__ float g_kqv[(size_t)TB * TT * C3];   // [B*T, 3C]  (k | q | v), fp32

// Fragment-major bf16 hi/lo planes (mma register layout in gmem).
__device__ uint4 g_xAh [(size_t)256 * 64 * 32];   // x      A-frags
__device__ uint4 g_xAl [(size_t)256 * 64 * 32];
__device__ uint4 g_atAh[(size_t)256 * 64 * 32];   // attn out A-frags (gemm2 input)
__device__ uint4 g_atAl[(size_t)256 * 64 * 32];
__device__ uint2 g_WkBh[(size_t)384 * 64 * 32];   // W_kqv  B-frags
__device__ uint2 g_WkBl[(size_t)384 * 64 * 32];
__device__ uint2 g_WpBh[(size_t)128 * 64 * 32];   // W_proj B-frags
__device__ uint2 g_WpBl[(size_t)128 * 64 * 32];

// Attention planes, per (b,h):
// Q A-frags (scaled 1/8): [BH][q16 0..127][kf 0..3][lane]   uint4
__device__ uint4 g_QAh[(size_t)32 * 128 * 4 * 32];
__device__ uint4 g_QAl[(size_t)32 * 128 * 4 * 32];
// K B-frags: [BH][kt 0..31][nf 0..7][kf 0..3][lane]          uint2 (tile = 8KB contiguous)
__device__ uint2 g_KBh[(size_t)32 * 32 * 8 * 4 * 32];
__device__ uint2 g_KBl[(size_t)32 * 32 * 8 * 4 * 32];
// V B-frags (transposed, n=d, k=key): [BH][kt][nf(d)][kf2(key)][lane] uint2
__device__ uint2 g_VBh[(size_t)32 * 32 * 8 * 4 * 32];
__device__ uint2 g_VBl[(size_t)32 * 32 * 8 * 4 * 32];

// ===========================================================================
// PTX helpers
// ===========================================================================
static __device__ __forceinline__ void mma16816(float* d, const uint4& a, const uint2& b) {
    asm volatile(
        "mma.sync.aligned.m16n8k16.row.col.f32.bf16.bf16.f32 "
        "{%0,%1,%2,%3}, {%4,%5,%6,%7}, {%8,%9}, {%0,%1,%2,%3};"
        : "+f"(d[0]), "+f"(d[1]), "+f"(d[2]), "+f"(d[3])
        : "r"(a.x), "r"(a.y), "r"(a.z), "r"(a.w), "r"(b.x), "r"(b.y));
}

static __device__ __forceinline__ void split2(float2 f, uint32_t& h, uint32_t& l) {
    __nv_bfloat162 hp = __floats2bfloat162_rn(f.x, f.y);
    float2 hf = __bfloat1622float2(hp);
    __nv_bfloat162 lp = __floats2bfloat162_rn(f.x - hf.x, f.y - hf.y);
    h = *reinterpret_cast<uint32_t*>(&hp);
    l = *reinterpret_cast<uint32_t*>(&lp);
}

static __device__ __forceinline__ uint32_t smem_u32(const void* p) {
    uint32_t a;
    asm("{ .reg .u64 t; cvta.to.shared.u64 t, %1; cvt.u32.u64 %0, t; }"
        : "=r"(a) : "l"(p));
    return a;
}

#define CP16(dst, src) \
    asm volatile("cp.async.cg.shared.global [%0], [%1], 16;" :: "r"(dst), "l"(src))
#define CP_COMMIT() asm volatile("cp.async.commit_group;" ::: "memory")
#define CP_WAIT1()  asm volatile("cp.async.wait_group 1;" ::: "memory")
#define CP_WAIT0()  asm volatile("cp.async.wait_group 0;" ::: "memory")

// ===========================================================================
// Prep kernels (fp32 row-major -> fragment-major bf16 hi/lo)
// ===========================================================================
__global__ __launch_bounds__(256)
void prep_a(const float* __restrict__ src, uint4* __restrict__ hi, uint4* __restrict__ lo)
{
    int slot = blockIdx.x * 256 + threadIdx.x;
    int frag = slot >> 5, la = slot & 31;
    int row = ((frag >> 6) << 4) + (la >> 2);
    int k   = ((frag & 63) << 4) + ((la & 3) << 1);
    const float* p = src + (size_t)row * 1024 + k;
    float2 x0 = *(const float2*)p;
    float2 x1 = *(const float2*)(p + 8 * 1024);
    float2 x2 = *(const float2*)(p + 8);
    float2 x3 = *(const float2*)(p + 8 * 1024 + 8);
    uint4 h, l;
    split2(x0, h.x, l.x);
    split2(x1, h.y, l.y);
    split2(x2, h.z, l.z);
    split2(x3, h.w, l.w);
    hi[slot] = h;
    lo[slot] = l;
}

__global__ __launch_bounds__(256)
void prep_b(const float* __restrict__ src, uint2* __restrict__ hi, uint2* __restrict__ lo)
{
    int slot = blockIdx.x * 256 + threadIdx.x;
    int frag = slot >> 5, la = slot & 31;
    int n = ((frag >> 6) << 3) + (la >> 2);
    int k = ((frag & 63) << 4) + ((la & 3) << 1);
    const float* p = src + (size_t)n * 1024 + k;
    float2 x0 = *(const float2*)p;
    float2 x1 = *(const float2*)(p + 8);
    uint2 h, l;
    split2(x0, h.x, l.x);
    split2(x1, h.y, l.y);
    hi[slot] = h;
    lo[slot] = l;
}

// Q plane: scale 1/8 folded in (exact). grid 2048 x 256.
__global__ __launch_bounds__(256)
void prep_q()
{
    int slot = blockIdx.x * 256 + threadIdx.x;      // 0..524287
    int la = slot & 31, frag = slot >> 5;
    int kf  = frag & 3;
    int q16 = (frag >> 2) & 127;
    int BH  = frag >> 9;
    int h = BH & 15, b = BH >> 4;
    int row = q16 * 16 + (la >> 2);
    int d0  = kf * 16 + (la & 3) * 2;
    const float* p = g_kqv + ((size_t)b * TT + row) * C3 + NE + h * HD + d0;
    float2 x0 = *(const float2*)p;
    float2 x1 = *(const float2*)(p + 8 * C3);
    float2 x2 = *(const float2*)(p + 8);
    float2 x3 = *(const float2*)(p + 8 * C3 + 8);
    x0.x *= 0.125f; x0.y *= 0.125f;
    x1.x *= 0.125f; x1.y *= 0.125f;
    x2.x *= 0.125f; x2.y *= 0.125f;
    x3.x *= 0.125f; x3.y *= 0.125f;
    uint4 h4, l4;
    split2(x0, h4.x, l4.x);
    split2(x1, h4.y, l4.y);
    split2(x2, h4.z, l4.z);
    split2(x3, h4.w, l4.w);
    g_QAh[slot] = h4;
    g_QAl[slot] = l4;
}

// K plane. grid 4096 x 256.
__global__ __launch_bounds__(256)
void prep_k()
{
    int slot = blockIdx.x * 256 + threadIdx.x;      // 0..1048575
    int la = slot & 31, frag = slot >> 5;
    int kf = frag & 3;
    int nf = (frag >> 2) & 7;
    int kt = (frag >> 5) & 31;
    int BH = frag >> 10;
    int h = BH & 15, b = BH >> 4;
    int key = kt * 64 + nf * 8 + (la >> 2);
    int d0  = kf * 16 + (la & 3) * 2;
    const float* p = g_kqv + ((size_t)b * TT + key) * C3 + h * HD + d0;
    float2 x0 = *(const float2*)p;
    float2 x1 = *(const float2*)(p + 8);
    uint2 hh, ll;
    split2(x0, hh.x, ll.x);
    split2(x1, hh.y, ll.y);
    g_KBh[slot] = hh;
    g_KBl[slot] = ll;
}

// V plane (transposed: n=d, k=key). grid 4096 x 256.
__global__ __launch_bounds__(256)
void prep_v()
{
    int slot = blockIdx.x * 256 + threadIdx.x;
    int la = slot & 31, frag = slot >> 5;
    int kf2 = frag & 3;
    int nf  = (frag >> 2) & 7;
    int kt  = (frag >> 5) & 31;
    int BH  = frag >> 10;
    int h = BH & 15, b = BH >> 4;
    int d  = nf * 8 + (la >> 2);
    int k0 = kt * 64 + kf2 * 16 + (la & 3) * 2;
    const float* base = g_kqv + (size_t)b * TT * C3 + 2 * NE + h * HD + d;
    float v00 = base[(size_t)k0 * C3];
    float v01 = base[(size_t)(k0 + 1) * C3];
    float v10 = base[(size_t)(k0 + 8) * C3];
    float v11 = base[(size_t)(k0 + 9) * C3];
    uint2 hh, ll;
    split2(make_float2(v00, v01), hh.x, ll.x);
    split2(make_float2(v10, v11), hh.y, ll.y);
    g_VBh[slot] = hh;
    g_VBl[slot] = ll;
}

// ===========================================================================
// GEMM via mma.sync from pre-split fragment-major bf16 (unchanged, 65% tensor)
// ===========================================================================
#define GSTAGE 32768
#define GSMEM  (2 * GSTAGE)

__global__ __launch_bounds__(256, 2)
void gemm_bf(const uint4* __restrict__ Ah, const uint4* __restrict__ Al,
             const uint2* __restrict__ Bh, const uint2* __restrict__ Bl,
             const float* __restrict__ bias, float* __restrict__ Cout, int N)
{
    extern __shared__ char smem[];
    const uint32_t sb = smem_u32(smem);
    const int tid = threadIdx.x;
    const int la  = tid & 31;
    const int wrp = tid >> 5;
    const int wm  = wrp >> 2;
    const int wn  = wrp & 3;
    const int r16b = blockIdx.y * 8;
    const int n8b  = blockIdx.x * 16;

    float acc[4][4][4];
#pragma unroll
    for (int i = 0; i < 4; i++)
#pragma unroll
        for (int j = 0; j < 4; j++)
#pragma unroll
            for (int r = 0; r < 4; r++) acc[i][j][r] = 0.f;

    auto issue = [&](int stage, int kc) {
        uint32_t base = sb + stage * GSTAGE;
#pragma unroll
        for (int rep = 0; rep < 2; rep++) {
            int u = rep * 256 + tid;
            int f = u >> 5, ln = u & 31;
            int ga = ((r16b + (f >> 1)) << 6) + (kc << 1) + (f & 1);
            CP16(base + f * 512 + ln * 16,        Ah + (size_t)ga * 32 + ln);
            CP16(base + 8192 + f * 512 + ln * 16, Al + (size_t)ga * 32 + ln);
        }
#pragma unroll
        for (int rep = 0; rep < 2; rep++) {
            int u = rep * 256 + tid;
            int f = u >> 4, j = u & 15;
            int gb = ((n8b + (f >> 1)) << 6) + (kc << 1) + (f & 1);
            CP16(base + 16384 + f * 256 + j * 16,
                 (const uint4*)Bh + (size_t)gb * 16 + j);
            CP16(base + 24576 + f * 256 + j * 16,
                 (const uint4*)Bl + (size_t)gb * 16 + j);
        }
        CP_COMMIT();
    };

    auto compute = [&](int stage) {
        char* base = smem + stage * GSTAGE;
#pragma unroll
        for (int kf = 0; kf < 2; kf++) {
            uint4 ah[4], al[4];
            uint2 bh[4], bl[4];
#pragma unroll
            for (int i = 0; i < 4; i++) {
                int foff = ((wm * 4 + i) * 2 + kf) * 512 + la * 16;
                ah[i] = *(const uint4*)(base + foff);
                al[i] = *(const uint4*)(base + 8192 + foff);
            }
#pragma unroll
            for (int j = 0; j < 4; j++) {
                int boff = ((wn * 4 + j) * 2 + kf) * 256 + la * 8;
                bh[j] = *(const uint2*)(base + 16384 + boff);
                bl[j] = *(const uint2*)(base + 24576 + boff);
            }
#pragma unroll
            for (int i = 0; i < 4; i++)
#pragma unroll
                for (int j = 0; j < 4; j++) {
                    mma16816(acc[i][j], ah[i], bh[j]);
                    mma16816(acc[i][j], ah[i], bl[j]);
                    mma16816(acc[i][j], al[i], bh[j]);
                }
        }
    };

    issue(0, 0);

    for (int kc = 0; kc < 32; kc++) {
        if (kc < 31) {
            issue((kc + 1) & 1, kc + 1);
            CP_WAIT1();
        } else {
            CP_WAIT0();
        }
        __syncthreads();
        compute(kc & 1);
        __syncthreads();
    }

    const int brow = blockIdx.y * 128;
    const int bcol = blockIdx.x * 128;
#pragma unroll
    for (int j = 0; j < 4; j++) {
        int c0 = bcol + wn * 32 + j * 8 + (la & 3) * 2;
        float bx = 0.f, by = 0.f;
        if (bias) { bx = bias[c0]; by = bias[c0 + 1]; }
#pragma unroll
        for (int i = 0; i < 4; i++) {
            int r0 = brow + wm * 64 + i * 16 + (la >> 2);
            float2 o0, o1;
            o0.x = acc[i][j][0] + bx; o0.y = acc[i][j][1] + by;
            o1.x = acc[i][j][2] + bx; o1.y = acc[i][j][3] + by;
            *(float2*)&Cout[(size_t)r0 * N + c0]       = o0;
            *(float2*)&Cout[(size_t)(r0 + 8) * N + c0] = o1;
        }
    }
}

// ===========================================================================
// Flash attention v2: cp.async pre-split frags, double-buffered tiles,
// epilogue writes gemm2 A-frag planes directly.
// smem: stage0 [0,32K) stage1 [32K,64K): KH | KL | VH | VL (8KB each)
//       QH [64K, 80K), QL [80K, 96K)
// ===========================================================================
#define ASTAGE   32768
#define AQH_OFF  65536
#define AQL_OFF  81920
#define ATTN_SMEM 98304

__global__ __launch_bounds__(256, 2)
void attn_mma2()
{
    const int qt = 15 - blockIdx.x;   // heavy CTAs first
    const int h  = blockIdx.y;
    const int b  = blockIdx.z;
    const int BH = b * 16 + h;

    extern __shared__ char smem[];
    const uint32_t sb = smem_u32(smem);

    const int tid = threadIdx.x;
    const int la  = tid & 31;
    const int w   = tid >> 5;
    const int r_in  = la >> 2;
    const int cpair = (la & 3) * 2;
    const int qbase = qt * 128;
    const int row0  = qbase + w * 16 + r_in;
    const int row1  = row0 + 8;

    // --- issue Q fragments (one group) ---
    {
        size_t qb = ((size_t)BH * 128 + qt * 8) * 128;   // uint4 units
#pragma unroll
        for (int rep = 0; rep < 4; rep++) {
            int u = rep * 256 + tid;                      // 0..1023
            CP16(sb + AQH_OFF + u * 16, g_QAh + qb + u);
            CP16(sb + AQL_OFF + u * 16, g_QAl + qb + u);
        }
        CP_COMMIT();
    }

    auto issue_tile = [&](int stage, int kt) {
        uint32_t base = sb + stage * ASTAGE;
        size_t t = ((size_t)BH * 32 + kt) * 512;          // uint4 units per tile
#pragma unroll
        for (int rep = 0; rep < 2; rep++) {
            int u = rep * 256 + tid;                      // 0..511
            CP16(base + u * 16,         (const uint4*)g_KBh + t + u);
            CP16(base + 8192 + u * 16,  (const uint4*)g_KBl + t + u);
            CP16(base + 16384 + u * 16, (const uint4*)g_VBh + t + u);
            CP16(base + 24576 + u * 16, (const uint4*)g_VBl + t + u);
        }
        CP_COMMIT();
    };

    float o[8][4];
#pragma unroll
    for (int nf = 0; nf < 8; nf++)
#pragma unroll
        for (int r = 0; r < 4; r++) o[nf][r] = 0.f;
    float m0 = -1e30f, m1 = -1e30f, l0 = 0.f, l1 = 0.f;

    const int ntiles = 2 * qt + 2;
    issue_tile(0, 0);

    for (int kt = 0; kt < ntiles; kt++) {
        if (kt + 1 < ntiles) {
            issue_tile((kt + 1) & 1, kt + 1);
            CP_WAIT1();
        } else {
            CP_WAIT0();
        }
        __syncthreads();

        char* stg = smem + (kt & 1) * ASTAGE;
        const int kbase = kt * 64;

        // --- S = (Q/8) K^T  (split-3) ---
        float sfr[8][4];
#pragma unroll
        for (int nf = 0; nf < 8; nf++)
#pragma unroll
            for (int r = 0; r < 4; r++) sfr[nf][r] = 0.f;

#pragma unroll
        for (int kf = 0; kf < 4; kf++) {
            int qoff = ((w * 4 + kf) << 9) + (la << 4);
            uint4 qh = *(const uint4*)(smem + AQH_OFF + qoff);
            uint4 ql = *(const uint4*)(smem + AQL_OFF + qoff);
#pragma unroll
            for (int nf = 0; nf < 8; nf++) {
                int off = ((nf * 4 + kf) << 8) + (la << 3);
                uint2 kh = *(const uint2*)(stg + off);
                uint2 kl = *(const uint2*)(stg + 8192 + off);
                mma16816(sfr[nf], qh, kh);
                mma16816(sfr[nf], qh, kl);
                mma16816(sfr[nf], ql, kh);
            }
        }

        // --- causal mask ---
        if (kbase + 63 > qbase + w * 16) {
#pragma unroll
            for (int nf = 0; nf < 8; nf++) {
                int c = kbase + nf * 8 + cpair;
                if (c     > row0) sfr[nf][0] = -1e30f;
                if (c + 1 > row0) sfr[nf][1] = -1e30f;
                if (c     > row1) sfr[nf][2] = -1e30f;
                if (c + 1 > row1) sfr[nf][3] = -1e30f;
            }
        }

        // --- online softmax ---
        float mx0 = -1e30f, mx1 = -1e30f;
#pragma unroll
        for (int nf = 0; nf < 8; nf++) {
            mx0 = fmaxf(mx0, fmaxf(sfr[nf][0], sfr[nf][1]));
            mx1 = fmaxf(mx1, fmaxf(sfr[nf][2], sfr[nf][3]));
        }
        mx0 = fmaxf(mx0, __shfl_xor_sync(0xffffffffu, mx0, 1));
        mx0 = fmaxf(mx0, __shfl_xor_sync(0xffffffffu, mx0, 2));
        mx1 = fmaxf(mx1, __shfl_xor_sync(0xffffffffu, mx1, 1));
        mx1 = fmaxf(mx1, __shfl_xor_sync(0xffffffffu, mx1, 2));

        float mn0 = fmaxf(m0, mx0), mn1 = fmaxf(m1, mx1);
        float a0 = __expf(m0 - mn0), a1 = __expf(m1 - mn1);
        float s0 = 0.f, s1 = 0.f;
#pragma unroll
        for (int nf = 0; nf < 8; nf++) {
            sfr[nf][0] = __expf(sfr[nf][0] - mn0);
            sfr[nf][1] = __expf(sfr[nf][1] - mn0);
            sfr[nf][2] = __expf(sfr[nf][2] - mn1);
            sfr[nf][3] = __expf(sfr[nf][3] - mn1);
            s0 += sfr[nf][0] + sfr[nf][1];
            s1 += sfr[nf][2] + sfr[nf][3];
        }
        s0 += __shfl_xor_sync(0xffffffffu, s0, 1);
        s0 += __shfl_xor_sync(0xffffffffu, s0, 2);
        s1 += __shfl_xor_sync(0xffffffffu, s1, 1);
        s1 += __shfl_xor_sync(0xffffffffu, s1, 2);

        l0 = l0 * a0 + s0;  l1 = l1 * a1 + s1;
        m0 = mn0;           m1 = mn1;
#pragma unroll
        for (int nf = 0; nf < 8; nf++) {
            o[nf][0] *= a0; o[nf][1] *= a0;
            o[nf][2] *= a1; o[nf][3] *= a1;
        }

        // --- O += P V  (register-retag P; split-3) ---
#pragma unroll
        for (int kf2 = 0; kf2 < 4; kf2++) {
            uint4 Ph, Pl;
            split2(make_float2(sfr[2 * kf2][0],     sfr[2 * kf2][1]),     Ph.x, Pl.x);
            split2(make_float2(sfr[2 * kf2][2],     sfr[2 * kf2][3]),     Ph.y, Pl.y);
            split2(make_float2(sfr[2 * kf2 + 1][0], sfr[2 * kf2 + 1][1]), Ph.z, Pl.z);
            split2(make_float2(sfr[2 * kf2 + 1][2], sfr[2 * kf2 + 1][3]), Ph.w, Pl.w);
#pragma unroll
            for (int nf = 0; nf < 8; nf++) {
                int off = ((nf * 4 + kf2) << 8) + (la << 3);
                uint2 vh = *(const uint2*)(stg + 16384 + off);
                uint2 vl = *(const uint2*)(stg + 24576 + off);
                mma16816(o[nf], Ph, vh);
                mma16816(o[nf], Ph, vl);
                mma16816(o[nf], Pl, vh);
            }
        }
        __syncthreads();
    }

    // --- epilogue: write gemm2 A-frag planes directly (o / l, exact split) ---
    float i0 = 1.f / l0, i1 = 1.f / l1;
    const int r16 = b * 128 + qt * 8 + w;     // global 16-row tile index
#pragma unroll
    for (int nf = 0; nf < 8; nf += 2) {
        int kfg = h * 4 + (nf >> 1);          // global K-fragment index (K=1024)
        size_t slot = ((size_t)r16 * 64 + kfg) * 32 + la;
        uint4 ah, al;
        split2(make_float2(o[nf][0] * i0,     o[nf][1] * i0),     ah.x, al.x);
        split2(make_float2(o[nf][2] * i1,     o[nf][3] * i1),     ah.y, al.y);
        split2(make_float2(o[nf + 1][0] * i0, o[nf + 1][1] * i0), ah.z, al.z);
        split2(make_float2(o[nf + 1][2] * i1, o[nf + 1][3] * i1), ah.w, al.w);
        g_atAh[slot] = ah;
        g_atAl[slot] = al;
    }
}

// ---------------------------------------------------------------------------
// Launch
// ---------------------------------------------------------------------------
extern "C" void kernel_launch(void* const* d_in, const int* in_sizes, int n_in,
                              void* d_out, int out_size)
{
    const float* x = nullptr, *Wkqv = nullptr, *Wproj = nullptr, *bproj = nullptr;
    for (int i = 0; i < n_in; i++) {
        int sz = in_sizes[i];
        if      (sz == TB * TT * NE)      x     = (const float*)d_in[i];
        else if (sz == 3 * NE * NE)       Wkqv  = (const float*)d_in[i];
        else if (sz == NE * NE)           Wproj = (const float*)d_in[i];
        else if (sz == NE)                bproj = (const float*)d_in[i];
    }
    float* out = (float*)d_out;

    float* kqv;
    uint4 *xAh, *xAl, *atAh, *atAl;
    uint2 *WkBh, *WkBl, *WpBh, *WpBl;
    cudaGetSymbolAddress((void**)&kqv,  g_kqv);
    cudaGetSymbolAddress((void**)&xAh,  g_xAh);
    cudaGetSymbolAddress((void**)&xAl,  g_xAl);
    cudaGetSymbolAddress((void**)&atAh, g_atAh);
    cudaGetSymbolAddress((void**)&atAl, g_atAl);
    cudaGetSymbolAddress((void**)&WkBh, g_WkBh);
    cudaGetSymbolAddress((void**)&WkBl, g_WkBl);
    cudaGetSymbolAddress((void**)&WpBh, g_WpBh);
    cudaGetSymbolAddress((void**)&WpBl, g_WpBl);

    cudaFuncSetAttribute(gemm_bf,
                         cudaFuncAttributeMaxDynamicSharedMemorySize, GSMEM);
    cudaFuncSetAttribute(attn_mma2,
                         cudaFuncAttributeMaxDynamicSharedMemorySize, ATTN_SMEM);

    // Prep inputs: fragment-major bf16 hi/lo
    prep_a<<<2048, 256>>>(x, xAh, xAl);
    prep_b<<<3072, 256>>>(Wkqv, WkBh, WkBl);
    prep_b<<<1024, 256>>>(Wproj, WpBh, WpBl);

    // 1) KQV projection -> g_kqv (fp32)
    {
        dim3 grid(C3 / 128, 32);
        gemm_bf<<<grid, 256, GSMEM>>>(xAh, xAl, WkBh, WkBl, nullptr, kqv, C3);
    }

    // 1b) Split kqv into attention fragment planes
    prep_q<<<2048, 256>>>();
    prep_k<<<4096, 256>>>();
    prep_v<<<4096, 256>>>();

    // 2) Causal flash attention -> g_atA planes (gemm2 input)
    {
        dim3 grid(TT / 128, NH, TB);
        attn_mma2<<<grid, 256, ATTN_SMEM>>>();
    }

    // 3) Output projection + bias
    {
        dim3 grid(NE / 128, 32);
        gemm_bf<<<grid, 256, GSMEM>>>(atAh, atAl, WpBh, WpBl, bproj, out, NE);
    }
}

// round 7
// speedup vs baseline: 3.2424x; 1.0164x over previous
#include <cuda_runtime.h>
#include <cuda_bf16.h>
#include <math.h>
#include <stddef.h>
#include <stdint.h>

// Problem constants
#define TB 2
#define TT 2048
#define NE 1024
#define NH 16
#define HD 64
#define C3 (3 * NE)   // 3072

// Q scale: 1/sqrt(64) * log2(e)  (softmax runs in exp2 domain)
#define QSCALE 0.18033688011112042f

// Scratch (allocation-free rule: device globals)
__device__ float g_vtmp[(size_t)TB * TT * NE];    // V fp32 [B*T][1024]

// Fragment-major bf16 hi/lo planes (mma register layout in gmem).
__device__ uint4 g_xAh [(size_t)256 * 64 * 32];   // x      A-frags
__device__ uint4 g_xAl [(size_t)256 * 64 * 32];
__device__ uint4 g_atAh[(size_t)256 * 64 * 32];   // attn out A-frags (gemm2 input)
__device__ uint4 g_atAl[(size_t)256 * 64 * 32];
__device__ uint2 g_WkBh[(size_t)384 * 64 * 32];   // W_kqv  B-frags
__device__ uint2 g_WkBl[(size_t)384 * 64 * 32];
__device__ uint2 g_WpBh[(size_t)128 * 64 * 32];   // W_proj B-frags
__device__ uint2 g_WpBl[(size_t)128 * 64 * 32];

// Attention planes, per (b,h):
// Q A-frags (scaled QSCALE): [BH][q16 0..127][kf 0..3][lane]  uint4
__device__ uint4 g_QAh[(size_t)32 * 128 * 4 * 32];
__device__ uint4 g_QAl[(size_t)32 * 128 * 4 * 32];
// K B-frags: [BH][kt 0..31][nf 0..7][kf 0..3][lane]            uint2
__device__ uint2 g_KBh[(size_t)32 * 32 * 8 * 4 * 32];
__device__ uint2 g_KBl[(size_t)32 * 32 * 8 * 4 * 32];
// V B-frags (transposed, n=d, k=key): [BH][kt][nf(d)][kf2(key)][lane] uint2
__device__ uint2 g_VBh[(size_t)32 * 32 * 8 * 4 * 32];
__device__ uint2 g_VBl[(size_t)32 * 32 * 8 * 4 * 32];

// ===========================================================================
// PTX helpers
// ===========================================================================
static __device__ __forceinline__ void mma16816(float* d, const uint4& a, const uint2& b) {
    asm volatile(
        "mma.sync.aligned.m16n8k16.row.col.f32.bf16.bf16.f32 "
        "{%0,%1,%2,%3}, {%4,%5,%6,%7}, {%8,%9}, {%0,%1,%2,%3};"
        : "+f"(d[0]), "+f"(d[1]), "+f"(d[2]), "+f"(d[3])
        : "r"(a.x), "r"(a.y), "r"(a.z), "r"(a.w), "r"(b.x), "r"(b.y));
}

static __device__ __forceinline__ void split2(float2 f, uint32_t& h, uint32_t& l) {
    __nv_bfloat162 hp = __floats2bfloat162_rn(f.x, f.y);
    float2 hf = __bfloat1622float2(hp);
    __nv_bfloat162 lp = __floats2bfloat162_rn(f.x - hf.x, f.y - hf.y);
    h = *reinterpret_cast<uint32_t*>(&hp);
    l = *reinterpret_cast<uint32_t*>(&lp);
}

static __device__ __forceinline__ float ex2(float x) {
    float r;
    asm("ex2.approx.f32 %0, %1;" : "=f"(r) : "f"(x));
    return r;
}

static __device__ __forceinline__ uint32_t smem_u32(const void* p) {
    uint32_t a;
    asm("{ .reg .u64 t; cvta.to.shared.u64 t, %1; cvt.u32.u64 %0, t; }"
        : "=r"(a) : "l"(p));
    return a;
}

#define CP16(dst, src) \
    asm volatile("cp.async.cg.shared.global [%0], [%1], 16;" :: "r"(dst), "l"(src))
#define CP_COMMIT() asm volatile("cp.async.commit_group;" ::: "memory")
#define CP_WAIT2()  asm volatile("cp.async.wait_group 2;" ::: "memory")
#define CP_WAIT1()  asm volatile("cp.async.wait_group 1;" ::: "memory")
#define CP_WAIT0()  asm volatile("cp.async.wait_group 0;" ::: "memory")

// ===========================================================================
// Prep kernels (fp32 row-major -> fragment-major bf16 hi/lo)
// ===========================================================================
__global__ __launch_bounds__(256)
void prep_a(const float* __restrict__ src, uint4* __restrict__ hi, uint4* __restrict__ lo)
{
    int slot = blockIdx.x * 256 + threadIdx.x;
    int frag = slot >> 5, la = slot & 31;
    int row = ((frag >> 6) << 4) + (la >> 2);
    int k   = ((frag & 63) << 4) + ((la & 3) << 1);
    const float* p = src + (size_t)row * 1024 + k;
    float2 x0 = *(const float2*)p;
    float2 x1 = *(const float2*)(p + 8 * 1024);
    float2 x2 = *(const float2*)(p + 8);
    float2 x3 = *(const float2*)(p + 8 * 1024 + 8);
    uint4 h, l;
    split2(x0, h.x, l.x);
    split2(x1, h.y, l.y);
    split2(x2, h.z, l.z);
    split2(x3, h.w, l.w);
    hi[slot] = h;
    lo[slot] = l;
}

__global__ __launch_bounds__(256)
void prep_b(const float* __restrict__ src, uint2* __restrict__ hi, uint2* __restrict__ lo)
{
    int slot = blockIdx.x * 256 + threadIdx.x;
    int frag = slot >> 5, la = slot & 31;
    int n = ((frag >> 6) << 3) + (la >> 2);
    int k = ((frag & 63) << 4) + ((la & 3) << 1);
    const float* p = src + (size_t)n * 1024 + k;
    float2 x0 = *(const float2*)p;
    float2 x1 = *(const float2*)(p + 8);
    uint2 h, l;
    split2(x0, h.x, l.x);
    split2(x1, h.y, l.y);
    hi[slot] = h;
    lo[slot] = l;
}

// V B-frag plane (transposed: n=d, k=key), from g_vtmp fp32. grid 4096 x 256.
__global__ __launch_bounds__(256)
void prep_v()
{
    int slot = blockIdx.x * 256 + threadIdx.x;
    int la = slot & 31, frag = slot >> 5;
    int kf2 = frag & 3;
    int nf  = (frag >> 2) & 7;
    int kt  = (frag >> 5) & 31;
    int BH  = frag >> 10;
    int h = BH & 15, b = BH >> 4;
    int d  = nf * 8 + (la >> 2);
    int k0 = kt * 64 + kf2 * 16 + (la & 3) * 2;
    const float* base = g_vtmp + (size_t)b * TT * NE + h * HD + d;
    float v00 = base[(size_t)k0 * NE];
    float v01 = base[(size_t)(k0 + 1) * NE];
    float v10 = base[(size_t)(k0 + 8) * NE];
    float v11 = base[(size_t)(k0 + 9) * NE];
    uint2 hh, ll;
    split2(make_float2(v00, v01), hh.x, ll.x);
    split2(make_float2(v10, v11), hh.y, ll.y);
    g_VBh[slot] = hh;
    g_VBl[slot] = ll;
}

// ===========================================================================
// GEMM via mma.sync from pre-split fragment-major bf16 (K = 1024).
// 3-stage cp.async pipeline. mode 0: fp32 out (+bias). mode 1: kqv fused —
// writes Q/K fragment planes by register retag, V fp32 to Cout (g_vtmp).
// ===========================================================================
#define GSTAGE 32768
#define GSMEM  (3 * GSTAGE)

__global__ __launch_bounds__(256, 2)
void gemm_bf(const uint4* __restrict__ Ah, const uint4* __restrict__ Al,
             const uint2* __restrict__ Bh, const uint2* __restrict__ Bl,
             const float* __restrict__ bias, float* __restrict__ Cout,
             int N, int mode)
{
    extern __shared__ char smem[];
    const uint32_t sb = smem_u32(smem);
    const int tid = threadIdx.x;
    const int la  = tid & 31;
    const int wrp = tid >> 5;
    const int wm  = wrp >> 2;
    const int wn  = wrp & 3;
    const int r16b = blockIdx.y * 8;
    const int n8b  = blockIdx.x * 16;

    float acc[4][4][4];
#pragma unroll
    for (int i = 0; i < 4; i++)
#pragma unroll
        for (int j = 0; j < 4; j++)
#pragma unroll
            for (int r = 0; r < 4; r++) acc[i][j][r] = 0.f;

    auto issue = [&](int stage, int kc) {
        uint32_t base = sb + stage * GSTAGE;
#pragma unroll
        for (int rep = 0; rep < 2; rep++) {
            int u = rep * 256 + tid;
            int f = u >> 5, ln = u & 31;
            int ga = ((r16b + (f >> 1)) << 6) + (kc << 1) + (f & 1);
            CP16(base + f * 512 + ln * 16,        Ah + (size_t)ga * 32 + ln);
            CP16(base + 8192 + f * 512 + ln * 16, Al + (size_t)ga * 32 + ln);
        }
#pragma unroll
        for (int rep = 0; rep < 2; rep++) {
            int u = rep * 256 + tid;
            int f = u >> 4, j = u & 15;
            int gb = ((n8b + (f >> 1)) << 6) + (kc << 1) + (f & 1);
            CP16(base + 16384 + f * 256 + j * 16,
                 (const uint4*)Bh + (size_t)gb * 16 + j);
            CP16(base + 24576 + f * 256 + j * 16,
                 (const uint4*)Bl + (size_t)gb * 16 + j);
        }
        CP_COMMIT();
    };

    auto compute = [&](int stage) {
        char* base = smem + stage * GSTAGE;
#pragma unroll
        for (int kf = 0; kf < 2; kf++) {
            uint4 ah[4], al[4];
            uint2 bh[4], bl[4];
#pragma unroll
            for (int i = 0; i < 4; i++) {
                int foff = ((wm * 4 + i) * 2 + kf) * 512 + la * 16;
                ah[i] = *(const uint4*)(base + foff);
                al[i] = *(const uint4*)(base + 8192 + foff);
            }
#pragma unroll
            for (int j = 0; j < 4; j++) {
                int boff = ((wn * 4 + j) * 2 + kf) * 256 + la * 8;
                bh[j] = *(const uint2*)(base + 16384 + boff);
                bl[j] = *(const uint2*)(base + 24576 + boff);
            }
#pragma unroll
            for (int i = 0; i < 4; i++)
#pragma unroll
                for (int j = 0; j < 4; j++) {
                    mma16816(acc[i][j], ah[i], bh[j]);
                    mma16816(acc[i][j], ah[i], bl[j]);
                    mma16816(acc[i][j], al[i], bh[j]);
                }
        }
    };

    issue(0, 0);
    issue(1, 1);

    for (int kc = 0; kc < 32; kc++) {
        if (kc + 2 < 32) {
            issue((kc + 2) % 3, kc + 2);
            CP_WAIT2();
        } else if (kc + 1 < 32) {
            CP_WAIT1();
        } else {
            CP_WAIT0();
        }
        __syncthreads();
        compute(kc % 3);
        __syncthreads();
    }

    const int brow = blockIdx.y * 128;
    const int bcol = blockIdx.x * 128;

    if (mode == 0) {
        // plain fp32 epilogue (+bias)
#pragma unroll
        for (int j = 0; j < 4; j++) {
            int c0 = bcol + wn * 32 + j * 8 + (la & 3) * 2;
            float bx = 0.f, by = 0.f;
            if (bias) { bx = bias[c0]; by = bias[c0 + 1]; }
#pragma unroll
            for (int i = 0; i < 4; i++) {
                int r0 = brow + wm * 64 + i * 16 + (la >> 2);
                float2 o0, o1;
                o0.x = acc[i][j][0] + bx; o0.y = acc[i][j][1] + by;
                o1.x = acc[i][j][2] + bx; o1.y = acc[i][j][3] + by;
                *(float2*)&Cout[(size_t)r0 * N + c0]       = o0;
                *(float2*)&Cout[(size_t)(r0 + 8) * N + c0] = o1;
            }
        }
    } else {
        // fused kqv epilogue. cols [0,1024)=k, [1024,2048)=q, [2048,3072)=v
        int role = bcol >> 10;
        if (role == 2) {
            // V: fp32 to g_vtmp (Cout), width 1024
#pragma unroll
            for (int j = 0; j < 4; j++) {
                int c0 = (bcol - 2048) + wn * 32 + j * 8 + (la & 3) * 2;
#pragma unroll
                for (int i = 0; i < 4; i++) {
                    int r0 = brow + wm * 64 + i * 16 + (la >> 2);
                    float2 o0, o1;
                    o0.x = acc[i][j][0]; o0.y = acc[i][j][1];
                    o1.x = acc[i][j][2]; o1.y = acc[i][j][3];
                    *(float2*)&Cout[(size_t)r0 * NE + c0]       = o0;
                    *(float2*)&Cout[(size_t)(r0 + 8) * NE + c0] = o1;
                }
            }
        } else {
#pragma unroll
            for (int t = 0; t < 2; t++) {
                int gcol = (bcol & 1023) + wn * 32 + t * 16;
                int h  = gcol >> 6;
                int kf = (gcol >> 4) & 3;
#pragma unroll
                for (int i = 0; i < 4; i++) {
                    int grow = brow + wm * 64 + i * 16;
                    int b = grow >> 11, trow = grow & 2047;
                    int BH = b * 16 + h;
                    const float* a0 = acc[i][2 * t];
                    const float* a1 = acc[i][2 * t + 1];
                    if (role == 1) {
                        // Q A-frag, scale QSCALE
                        size_t slot = ((((size_t)BH * 128) + (trow >> 4)) * 4 + kf) * 32 + la;
                        uint4 ah, al;
                        split2(make_float2(a0[0] * QSCALE, a0[1] * QSCALE), ah.x, al.x);
                        split2(make_float2(a0[2] * QSCALE, a0[3] * QSCALE), ah.y, al.y);
                        split2(make_float2(a1[0] * QSCALE, a1[1] * QSCALE), ah.z, al.z);
                        split2(make_float2(a1[2] * QSCALE, a1[3] * QSCALE), ah.w, al.w);
                        g_QAh[slot] = ah;
                        g_QAl[slot] = al;
                    } else {
                        // K B-frags: nf = 2i (rows la>>2), 2i+1 (rows +8)
                        int kt = trow >> 6;
                        size_t fb = ((size_t)BH * 32 + kt) * 8;
                        size_t s0 = ((fb + 2 * i)     * 4 + kf) * 32 + la;
                        size_t s1 = ((fb + 2 * i + 1) * 4 + kf) * 32 + la;
                        uint2 h0, l0, h1, l1;
                        split2(make_float2(a0[0], a0[1]), h0.x, l0.x);
                        split2(make_float2(a1[0], a1[1]), h0.y, l0.y);
                        split2(make_float2(a0[2], a0[3]), h1.x, l1.x);
                        split2(make_float2(a1[2], a1[3]), h1.y, l1.y);
                        g_KBh[s0] = h0; g_KBl[s0] = l0;
                        g_KBh[s1] = h1; g_KBl[s1] = l1;
                    }
                }
            }
        }
    }
}

// ===========================================================================
// Flash attention v3: Q fragments in registers, exp2-domain softmax,
// 2-stage cp.async K/V tiles, masked-warp skip, direct A-frag epilogue.
// smem: stage0 [0,32K) stage1 [32K,64K): KH | KL | VH | VL (8KB each)
// ===========================================================================
#define ASTAGE   32768
#define ATTN_SMEM 65536

__global__ __launch_bounds__(256, 2)
void attn_mma3()
{
    const int qt = 15 - blockIdx.x;   // heavy CTAs first
    const int h  = blockIdx.y;
    const int b  = blockIdx.z;
    const int BH = b * 16 + h;

    extern __shared__ char smem[];
    const uint32_t sb = smem_u32(smem);

    const int tid = threadIdx.x;
    const int la  = tid & 31;
    const int w   = tid >> 5;
    const int r_in  = la >> 2;
    const int cpair = (la & 3) * 2;
    const int qbase = qt * 128;
    const int row0  = qbase + w * 16 + r_in;
    const int row1  = row0 + 8;

    // Q fragments: registers, loaded once (scale pre-folded)
    uint4 Qh[4], Ql[4];
    {
        size_t qb = (((size_t)BH * 128 + qt * 8 + w) * 4) * 32 + la;
#pragma unroll
        for (int kf = 0; kf < 4; kf++) {
            Qh[kf] = g_QAh[qb + kf * 32];
            Ql[kf] = g_QAl[qb + kf * 32];
        }
    }

    auto issue_tile = [&](int stage, int kt) {
        uint32_t base = sb + stage * ASTAGE;
        size_t t = ((size_t)BH * 32 + kt) * 512;   // uint4 units per tile
#pragma unroll
        for (int rep = 0; rep < 2; rep++) {
            int u = rep * 256 + tid;               // 0..511
            CP16(base + u * 16,         (const uint4*)g_KBh + t + u);
            CP16(base + 8192 + u * 16,  (const uint4*)g_KBl + t + u);
            CP16(base + 16384 + u * 16, (const uint4*)g_VBh + t + u);
            CP16(base + 24576 + u * 16, (const uint4*)g_VBl + t + u);
        }
        CP_COMMIT();
    };

    float o[8][4];
#pragma unroll
    for (int nf = 0; nf < 8; nf++)
#pragma unroll
        for (int r = 0; r < 4; r++) o[nf][r] = 0.f;
    float m0 = -1e30f, m1 = -1e30f, l0 = 0.f, l1 = 0.f;

    const int ntiles = 2 * qt + 2;
    issue_tile(0, 0);

    for (int kt = 0; kt < ntiles; kt++) {
        if (kt + 1 < ntiles) {
            issue_tile((kt + 1) & 1, kt + 1);
            CP_WAIT1();
        } else {
            CP_WAIT0();
        }
        __syncthreads();

        char* stg = smem + (kt & 1) * ASTAGE;
        const int kbase = kt * 64;

        // warp fully masked? (diagonal region only)
        if (kbase <= qbase + w * 16 + 15) {
            // --- S = Q K^T  (split-3; Q scaled by 1/8*log2e) ---
            float sfr[8][4];
#pragma unroll
            for (int nf = 0; nf < 8; nf++)
#pragma unroll
                for (int r = 0; r < 4; r++) sfr[nf][r] = 0.f;

#pragma unroll
            for (int kf = 0; kf < 4; kf++) {
#pragma unroll
                for (int nf = 0; nf < 8; nf++) {
                    int off = ((nf * 4 + kf) << 8) + (la << 3);
                    uint2 kh = *(const uint2*)(stg + off);
                    uint2 kl = *(const uint2*)(stg + 8192 + off);
                    mma16816(sfr[nf], Qh[kf], kh);
                    mma16816(sfr[nf], Qh[kf], kl);
                    mma16816(sfr[nf], Ql[kf], kh);
                }
            }

            // --- causal mask ---
            if (kbase + 63 > qbase + w * 16) {
#pragma unroll
                for (int nf = 0; nf < 8; nf++) {
                    int c = kbase + nf * 8 + cpair;
                    if (c     > row0) sfr[nf][0] = -1e30f;
                    if (c + 1 > row0) sfr[nf][1] = -1e30f;
                    if (c     > row1) sfr[nf][2] = -1e30f;
                    if (c + 1 > row1) sfr[nf][3] = -1e30f;
                }
            }

            // --- online softmax (exp2 domain) ---
            float mx0 = -1e30f, mx1 = -1e30f;
#pragma unroll
            for (int nf = 0; nf < 8; nf++) {
                mx0 = fmaxf(mx0, fmaxf(sfr[nf][0], sfr[nf][1]));
                mx1 = fmaxf(mx1, fmaxf(sfr[nf][2], sfr[nf][3]));
            }
            mx0 = fmaxf(mx0, __shfl_xor_sync(0xffffffffu, mx0, 1));
            mx0 = fmaxf(mx0, __shfl_xor_sync(0xffffffffu, mx0, 2));
            mx1 = fmaxf(mx1, __shfl_xor_sync(0xffffffffu, mx1, 1));
            mx1 = fmaxf(mx1, __shfl_xor_sync(0xffffffffu, mx1, 2));

            float mn0 = fmaxf(m0, mx0), mn1 = fmaxf(m1, mx1);
            float a0 = ex2(m0 - mn0), a1 = ex2(m1 - mn1);
            float s0 = 0.f, s1 = 0.f;
#pragma unroll
            for (int nf = 0; nf < 8; nf++) {
                sfr[nf][0] = ex2(sfr[nf][0] - mn0);
                sfr[nf][1] = ex2(sfr[nf][1] - mn0);
                sfr[nf][2] = ex2(sfr[nf][2] - mn1);
                sfr[nf][3] = ex2(sfr[nf][3] - mn1);
                s0 += sfr[nf][0] + sfr[nf][1];
                s1 += sfr[nf][2] + sfr[nf][3];
            }
            s0 += __shfl_xor_sync(0xffffffffu, s0, 1);
            s0 += __shfl_xor_sync(0xffffffffu, s0, 2);
            s1 += __shfl_xor_sync(0xffffffffu, s1, 1);
            s1 += __shfl_xor_sync(0xffffffffu, s1, 2);

            l0 = l0 * a0 + s0;  l1 = l1 * a1 + s1;
            m0 = mn0;           m1 = mn1;
#pragma unroll
            for (int nf = 0; nf < 8; nf++) {
                o[nf][0] *= a0; o[nf][1] *= a0;
                o[nf][2] *= a1; o[nf][3] *= a1;
            }

            // --- O += P V  (register-retag P; split-3) ---
#pragma unroll
            for (int kf2 = 0; kf2 < 4; kf2++) {
                uint4 Ph, Pl;
                split2(make_float2(sfr[2 * kf2][0],     sfr[2 * kf2][1]),     Ph.x, Pl.x);
                split2(make_float2(sfr[2 * kf2][2],     sfr[2 * kf2][3]),     Ph.y, Pl.y);
                split2(make_float2(sfr[2 * kf2 + 1][0], sfr[2 * kf2 + 1][1]), Ph.z, Pl.z);
                split2(make_float2(sfr[2 * kf2 + 1][2], sfr[2 * kf2 + 1][3]), Ph.w, Pl.w);
#pragma unroll
                for (int nf = 0; nf < 8; nf++) {
                    int off = ((nf * 4 + kf2) << 8) + (la << 3);
                    uint2 vh = *(const uint2*)(stg + 16384 + off);
                    uint2 vl = *(const uint2*)(stg + 24576 + off);
                    mma16816(o[nf], Ph, vh);
                    mma16816(o[nf], Ph, vl);
                    mma16816(o[nf], Pl, vh);
                }
            }
        }
        __syncthreads();
    }

    // --- epilogue: write gemm2 A-frag planes directly (o / l) ---
    float i0 = 1.f / l0, i1 = 1.f / l1;
    const int r16 = b * 128 + qt * 8 + w;
#pragma unroll
    for (int nf = 0; nf < 8; nf += 2) {
        int kfg = h * 4 + (nf >> 1);
        size_t slot = ((size_t)r16 * 64 + kfg) * 32 + la;
        uint4 ah, al;
        split2(make_float2(o[nf][0] * i0,     o[nf][1] * i0),     ah.x, al.x);
        split2(make_float2(o[nf][2] * i1,     o[nf][3] * i1),     ah.y, al.y);
        split2(make_float2(o[nf + 1][0] * i0, o[nf + 1][1] * i0), ah.z, al.z);
        split2(make_float2(o[nf + 1][2] * i1, o[nf + 1][3] * i1), ah.w, al.w);
        g_atAh[slot] = ah;
        g_atAl[slot] = al;
    }
}

// ---------------------------------------------------------------------------
// Launch
// ---------------------------------------------------------------------------
extern "C" void kernel_launch(void* const* d_in, const int* in_sizes, int n_in,
                              void* d_out, int out_size)
{
    const float* x = nullptr, *Wkqv = nullptr, *Wproj = nullptr, *bproj = nullptr;
    for (int i = 0; i < n_in; i++) {
        int sz = in_sizes[i];
        if      (sz == TB * TT * NE)      x     = (const float*)d_in[i];
        else if (sz == 3 * NE * NE)       Wkqv  = (const float*)d_in[i];
        else if (sz == NE * NE)           Wproj = (const float*)d_in[i];
        else if (sz == NE)                bproj = (const float*)d_in[i];
    }
    float* out = (float*)d_out;

    float* vtmp;
    uint4 *xAh, *xAl, *atAh, *atAl;
    uint2 *WkBh, *WkBl, *WpBh, *WpBl;
    cudaGetSymbolAddress((void**)&vtmp, g_vtmp);
    cudaGetSymbolAddress((void**)&xAh,  g_xAh);
    cudaGetSymbolAddress((void**)&xAl,  g_xAl);
    cudaGetSymbolAddress((void**)&atAh, g_atAh);
    cudaGetSymbolAddress((void**)&atAl, g_atAl);
    cudaGetSymbolAddress((void**)&WkBh, g_WkBh);
    cudaGetSymbolAddress((void**)&WkBl, g_WkBl);
    cudaGetSymbolAddress((void**)&WpBh, g_WpBh);
    cudaGetSymbolAddress((void**)&WpBl, g_WpBl);

    cudaFuncSetAttribute(gemm_bf,
                         cudaFuncAttributeMaxDynamicSharedMemorySize, GSMEM);
    cudaFuncSetAttribute(attn_mma3,
                         cudaFuncAttributeMaxDynamicSharedMemorySize, ATTN_SMEM);

    // Prep inputs: fragment-major bf16 hi/lo
    prep_a<<<2048, 256>>>(x, xAh, xAl);
    prep_b<<<3072, 256>>>(Wkqv, WkBh, WkBl);
    prep_b<<<1024, 256>>>(Wproj, WpBh, WpBl);

    // 1) KQV projection, fused epilogue -> Q/K frag planes + V fp32
    {
        dim3 grid(C3 / 128, 32);
        gemm_bf<<<grid, 256, GSMEM>>>(xAh, xAl, WkBh, WkBl, nullptr, vtmp, NE, 1);
    }

    // 1b) V fragment plane
    prep_v<<<4096, 256>>>();

    // 2) Causal flash attention -> g_atA planes
    {
        dim3 grid(TT / 128, NH, TB);
        attn_mma3<<<grid, 256, ATTN_SMEM>>>();
    }

    // 3) Output projection + bias
    {
        dim3 grid(NE / 128, 32);
        gemm_bf<<<grid, 256, GSMEM>>>(atAh, atAl, WpBh, WpBl, bproj, out, NE, 0);
    }
}

// round 8
// speedup vs baseline: 3.4346x; 1.0593x over previous
#include <cuda_runtime.h>
#include <cuda_bf16.h>
#include <math.h>
#include <stddef.h>
#include <stdint.h>

// Problem constants
#define TB 2
#define TT 2048
#define NE 1024
#define NH 16
#define HD 64
#define C3 (3 * NE)   // 3072

// Q scale: 1/sqrt(64) * log2(e)  (softmax runs in exp2 domain)
#define QSCALE 0.18033688011112042f

// Scratch (allocation-free rule: device globals)
__device__ float g_vtmp[(size_t)TB * TT * NE];    // V fp32 [B*T][1024]

// Fragment-major bf16 hi/lo planes (mma register layout in gmem).
__device__ uint4 g_xAh [(size_t)256 * 64 * 32];   // x      A-frags
__device__ uint4 g_xAl [(size_t)256 * 64 * 32];
__device__ uint4 g_atAh[(size_t)256 * 64 * 32];   // attn out A-frags (gemm2 input)
__device__ uint4 g_atAl[(size_t)256 * 64 * 32];
__device__ uint2 g_WkBh[(size_t)384 * 64 * 32];   // W_kqv  B-frags
__device__ uint2 g_WkBl[(size_t)384 * 64 * 32];
__device__ uint2 g_WpBh[(size_t)128 * 64 * 32];   // W_proj B-frags
__device__ uint2 g_WpBl[(size_t)128 * 64 * 32];

// Attention planes, per (b,h):
__device__ uint4 g_QAh[(size_t)32 * 128 * 4 * 32];
__device__ uint4 g_QAl[(size_t)32 * 128 * 4 * 32];
__device__ uint2 g_KBh[(size_t)32 * 32 * 8 * 4 * 32];
__device__ uint2 g_KBl[(size_t)32 * 32 * 8 * 4 * 32];
__device__ uint2 g_VBh[(size_t)32 * 32 * 8 * 4 * 32];
__device__ uint2 g_VBl[(size_t)32 * 32 * 8 * 4 * 32];

// ===========================================================================
// PTX helpers
// ===========================================================================
static __device__ __forceinline__ void mma16816(float* d, const uint4& a, const uint2& b) {
    asm volatile(
        "mma.sync.aligned.m16n8k16.row.col.f32.bf16.bf16.f32 "
        "{%0,%1,%2,%3}, {%4,%5,%6,%7}, {%8,%9}, {%0,%1,%2,%3};"
        : "+f"(d[0]), "+f"(d[1]), "+f"(d[2]), "+f"(d[3])
        : "r"(a.x), "r"(a.y), "r"(a.z), "r"(a.w), "r"(b.x), "r"(b.y));
}

static __device__ __forceinline__ void split2(float2 f, uint32_t& h, uint32_t& l) {
    __nv_bfloat162 hp = __floats2bfloat162_rn(f.x, f.y);
    float2 hf = __bfloat1622float2(hp);
    __nv_bfloat162 lp = __floats2bfloat162_rn(f.x - hf.x, f.y - hf.y);
    h = *reinterpret_cast<uint32_t*>(&hp);
    l = *reinterpret_cast<uint32_t*>(&lp);
}

static __device__ __forceinline__ float ex2(float x) {
    float r;
    asm("ex2.approx.f32 %0, %1;" : "=f"(r) : "f"(x));
    return r;
}

static __device__ __forceinline__ uint32_t smem_u32(const void* p) {
    uint32_t a;
    asm("{ .reg .u64 t; cvta.to.shared.u64 t, %1; cvt.u32.u64 %0, t; }"
        : "=r"(a) : "l"(p));
    return a;
}

#define CP16(dst, src) \
    asm volatile("cp.async.cg.shared.global [%0], [%1], 16;" :: "r"(dst), "l"(src))
#define CP_COMMIT() asm volatile("cp.async.commit_group;" ::: "memory")
#define CP_WAIT2()  asm volatile("cp.async.wait_group 2;" ::: "memory")
#define CP_WAIT1()  asm volatile("cp.async.wait_group 1;" ::: "memory")
#define CP_WAIT0()  asm volatile("cp.async.wait_group 0;" ::: "memory")

// ===========================================================================
// Prep kernels (fp32 row-major -> fragment-major bf16 hi/lo)
// ===========================================================================
__global__ __launch_bounds__(256)
void prep_a(const float* __restrict__ src, uint4* __restrict__ hi, uint4* __restrict__ lo)
{
    int slot = blockIdx.x * 256 + threadIdx.x;
    int frag = slot >> 5, la = slot & 31;
    int row = ((frag >> 6) << 4) + (la >> 2);
    int k   = ((frag & 63) << 4) + ((la & 3) << 1);
    const float* p = src + (size_t)row * 1024 + k;
    float2 x0 = *(const float2*)p;
    float2 x1 = *(const float2*)(p + 8 * 1024);
    float2 x2 = *(const float2*)(p + 8);
    float2 x3 = *(const float2*)(p + 8 * 1024 + 8);
    uint4 h, l;
    split2(x0, h.x, l.x);
    split2(x1, h.y, l.y);
    split2(x2, h.z, l.z);
    split2(x3, h.w, l.w);
    hi[slot] = h;
    lo[slot] = l;
}

__global__ __launch_bounds__(256)
void prep_b(const float* __restrict__ src, uint2* __restrict__ hi, uint2* __restrict__ lo)
{
    int slot = blockIdx.x * 256 + threadIdx.x;
    int frag = slot >> 5, la = slot & 31;
    int n = ((frag >> 6) << 3) + (la >> 2);
    int k = ((frag & 63) << 4) + ((la & 3) << 1);
    const float* p = src + (size_t)n * 1024 + k;
    float2 x0 = *(const float2*)p;
    float2 x1 = *(const float2*)(p + 8);
    uint2 h, l;
    split2(x0, h.x, l.x);
    split2(x1, h.y, l.y);
    hi[slot] = h;
    lo[slot] = l;
}

// V B-frag plane (transposed: n=d, k=key), from g_vtmp fp32. grid 4096 x 256.
__global__ __launch_bounds__(256)
void prep_v()
{
    int slot = blockIdx.x * 256 + threadIdx.x;
    int la = slot & 31, frag = slot >> 5;
    int kf2 = frag & 3;
    int nf  = (frag >> 2) & 7;
    int kt  = (frag >> 5) & 31;
    int BH  = frag >> 10;
    int h = BH & 15, b = BH >> 4;
    int d  = nf * 8 + (la >> 2);
    int k0 = kt * 64 + kf2 * 16 + (la & 3) * 2;
    const float* base = g_vtmp + (size_t)b * TT * NE + h * HD + d;
    float v00 = base[(size_t)k0 * NE];
    float v01 = base[(size_t)(k0 + 1) * NE];
    float v10 = base[(size_t)(k0 + 8) * NE];
    float v11 = base[(size_t)(k0 + 9) * NE];
    uint2 hh, ll;
    split2(make_float2(v00, v01), hh.x, ll.x);
    split2(make_float2(v10, v11), hh.y, ll.y);
    g_VBh[slot] = hh;
    g_VBl[slot] = ll;
}

// ===========================================================================
// GEMM via mma.sync, warp tile 64x64, 4 warps (2x2), 2 CTAs/SM.
// CTA tile 128x128, K = 1024, chunks of 32, 3-stage cp.async pipeline.
// Stage 32KB: Ah[16fr x512] Al Bh[32fr x256] Bl.
// mode 0: fp32 out (+bias). mode 1: fused kqv epilogue.
// ===========================================================================
#define GSTAGE 32768
#define GSMEM  (3 * GSTAGE)

__global__ __launch_bounds__(128, 2)
void gemm_bf(const uint4* __restrict__ Ah, const uint4* __restrict__ Al,
             const uint2* __restrict__ Bh, const uint2* __restrict__ Bl,
             const float* __restrict__ bias, float* __restrict__ Cout,
             int N, int mode)
{
    extern __shared__ char smem[];
    const uint32_t sb = smem_u32(smem);
    const int tid = threadIdx.x;
    const int la  = tid & 31;
    const int wrp = tid >> 5;   // 0..3
    const int wm  = wrp >> 1;   // 0..1
    const int wn  = wrp & 1;    // 0..1
    const int r16b = blockIdx.y * 8;
    const int n8b  = blockIdx.x * 16;

    float acc[4][8][4];
#pragma unroll
    for (int i = 0; i < 4; i++)
#pragma unroll
        for (int j = 0; j < 8; j++)
#pragma unroll
            for (int r = 0; r < 4; r++) acc[i][j][r] = 0.f;

    auto issue = [&](int stage, int kc) {
        uint32_t base = sb + stage * GSTAGE;
#pragma unroll
        for (int rep = 0; rep < 4; rep++) {
            int u = rep * 128 + tid;           // 0..511
            int f = u >> 5, ln = u & 31;
            int ga = ((r16b + (f >> 1)) << 6) + (kc << 1) + (f & 1);
            CP16(base + f * 512 + ln * 16,        Ah + (size_t)ga * 32 + ln);
            CP16(base + 8192 + f * 512 + ln * 16, Al + (size_t)ga * 32 + ln);
        }
#pragma unroll
        for (int rep = 0; rep < 4; rep++) {
            int u = rep * 128 + tid;           // 0..511
            int f = u >> 4, j = u & 15;
            int gb = ((n8b + (f >> 1)) << 6) + (kc << 1) + (f & 1);
            CP16(base + 16384 + f * 256 + j * 16,
                 (const uint4*)Bh + (size_t)gb * 16 + j);
            CP16(base + 24576 + f * 256 + j * 16,
                 (const uint4*)Bl + (size_t)gb * 16 + j);
        }
        CP_COMMIT();
    };

    auto compute = [&](int stage) {
        char* base = smem + stage * GSTAGE;
#pragma unroll
        for (int kf = 0; kf < 2; kf++) {
            uint4 ah[4], al[4];
#pragma unroll
            for (int i = 0; i < 4; i++) {
                int foff = ((wm * 4 + i) * 2 + kf) * 512 + la * 16;
                ah[i] = *(const uint4*)(base + foff);
                al[i] = *(const uint4*)(base + 8192 + foff);
            }
#pragma unroll
            for (int jg = 0; jg < 2; jg++) {
                uint2 bh[4], bl[4];
#pragma unroll
                for (int jj = 0; jj < 4; jj++) {
                    int boff = ((wn * 8 + jg * 4 + jj) * 2 + kf) * 256 + la * 8;
                    bh[jj] = *(const uint2*)(base + 16384 + boff);
                    bl[jj] = *(const uint2*)(base + 24576 + boff);
                }
#pragma unroll
                for (int i = 0; i < 4; i++)
#pragma unroll
                    for (int jj = 0; jj < 4; jj++) {
                        float* a = acc[i][jg * 4 + jj];
                        mma16816(a, ah[i], bh[jj]);
                        mma16816(a, ah[i], bl[jj]);
                        mma16816(a, al[i], bh[jj]);
                    }
            }
        }
    };

    issue(0, 0);
    issue(1, 1);

    for (int kc = 0; kc < 32; kc++) {
        if (kc + 2 < 32) {
            issue((kc + 2) % 3, kc + 2);
            CP_WAIT2();
        } else if (kc + 1 < 32) {
            CP_WAIT1();
        } else {
            CP_WAIT0();
        }
        __syncthreads();
        compute(kc % 3);
        __syncthreads();
    }

    const int brow = blockIdx.y * 128;
    const int bcol = blockIdx.x * 128;

    if (mode == 0) {
        // plain fp32 epilogue (+bias)
#pragma unroll
        for (int j = 0; j < 8; j++) {
            int c0 = bcol + wn * 64 + j * 8 + (la & 3) * 2;
            float bx = 0.f, by = 0.f;
            if (bias) { bx = bias[c0]; by = bias[c0 + 1]; }
#pragma unroll
            for (int i = 0; i < 4; i++) {
                int r0 = brow + wm * 64 + i * 16 + (la >> 2);
                float2 o0, o1;
                o0.x = acc[i][j][0] + bx; o0.y = acc[i][j][1] + by;
                o1.x = acc[i][j][2] + bx; o1.y = acc[i][j][3] + by;
                *(float2*)&Cout[(size_t)r0 * N + c0]       = o0;
                *(float2*)&Cout[(size_t)(r0 + 8) * N + c0] = o1;
            }
        }
    } else {
        // fused kqv epilogue. cols [0,1024)=k, [1024,2048)=q, [2048,3072)=v
        int role = bcol >> 10;
        if (role == 2) {
#pragma unroll
            for (int j = 0; j < 8; j++) {
                int c0 = (bcol - 2048) + wn * 64 + j * 8 + (la & 3) * 2;
#pragma unroll
                for (int i = 0; i < 4; i++) {
                    int r0 = brow + wm * 64 + i * 16 + (la >> 2);
                    float2 o0, o1;
                    o0.x = acc[i][j][0]; o0.y = acc[i][j][1];
                    o1.x = acc[i][j][2]; o1.y = acc[i][j][3];
                    *(float2*)&Cout[(size_t)r0 * NE + c0]       = o0;
                    *(float2*)&Cout[(size_t)(r0 + 8) * NE + c0] = o1;
                }
            }
        } else {
#pragma unroll
            for (int t = 0; t < 4; t++) {
                int gcol = (bcol & 1023) + wn * 64 + t * 16;
                int h  = gcol >> 6;
                int kf = (gcol >> 4) & 3;
#pragma unroll
                for (int i = 0; i < 4; i++) {
                    int grow = brow + wm * 64 + i * 16;
                    int b = grow >> 11, trow = grow & 2047;
                    int BH = b * 16 + h;
                    const float* a0 = acc[i][2 * t];
                    const float* a1 = acc[i][2 * t + 1];
                    if (role == 1) {
                        // Q A-frag, scale QSCALE
                        size_t slot = ((((size_t)BH * 128) + (trow >> 4)) * 4 + kf) * 32 + la;
                        uint4 ah4, al4;
                        split2(make_float2(a0[0] * QSCALE, a0[1] * QSCALE), ah4.x, al4.x);
                        split2(make_float2(a0[2] * QSCALE, a0[3] * QSCALE), ah4.y, al4.y);
                        split2(make_float2(a1[0] * QSCALE, a1[1] * QSCALE), ah4.z, al4.z);
                        split2(make_float2(a1[2] * QSCALE, a1[3] * QSCALE), ah4.w, al4.w);
                        g_QAh[slot] = ah4;
                        g_QAl[slot] = al4;
                    } else {
                        // K B-frags
                        int kt = trow >> 6;
                        size_t fb = ((size_t)BH * 32 + kt) * 8;
                        size_t s0 = ((fb + 2 * i)     * 4 + kf) * 32 + la;
                        size_t s1 = ((fb + 2 * i + 1) * 4 + kf) * 32 + la;
                        uint2 h0, l0, h1, l1;
                        split2(make_float2(a0[0], a0[1]), h0.x, l0.x);
                        split2(make_float2(a1[0], a1[1]), h0.y, l0.y);
                        split2(make_float2(a0[2], a0[3]), h1.x, l1.x);
                        split2(make_float2(a1[2], a1[3]), h1.y, l1.y);
                        g_KBh[s0] = h0; g_KBl[s0] = l0;
                        g_KBh[s1] = h1; g_KBl[s1] = l1;
                    }
                }
            }
        }
    }
}

// ===========================================================================
// Flash attention v3 (unchanged from round 7)
// ===========================================================================
#define ASTAGE   32768
#define ATTN_SMEM 65536

__global__ __launch_bounds__(256, 2)
void attn_mma3()
{
    const int qt = 15 - blockIdx.x;
    const int h  = blockIdx.y;
    const int b  = blockIdx.z;
    const int BH = b * 16 + h;

    extern __shared__ char smem[];
    const uint32_t sb = smem_u32(smem);

    const int tid = threadIdx.x;
    const int la  = tid & 31;
    const int w   = tid >> 5;
    const int r_in  = la >> 2;
    const int cpair = (la & 3) * 2;
    const int qbase = qt * 128;
    const int row0  = qbase + w * 16 + r_in;
    const int row1  = row0 + 8;

    uint4 Qh[4], Ql[4];
    {
        size_t qb = (((size_t)BH * 128 + qt * 8 + w) * 4) * 32 + la;
#pragma unroll
        for (int kf = 0; kf < 4; kf++) {
            Qh[kf] = g_QAh[qb + kf * 32];
            Ql[kf] = g_QAl[qb + kf * 32];
        }
    }

    auto issue_tile = [&](int stage, int kt) {
        uint32_t base = sb + stage * ASTAGE;
        size_t t = ((size_t)BH * 32 + kt) * 512;
#pragma unroll
        for (int rep = 0; rep < 2; rep++) {
            int u = rep * 256 + tid;
            CP16(base + u * 16,         (const uint4*)g_KBh + t + u);
            CP16(base + 8192 + u * 16,  (const uint4*)g_KBl + t + u);
            CP16(base + 16384 + u * 16, (const uint4*)g_VBh + t + u);
            CP16(base + 24576 + u * 16, (const uint4*)g_VBl + t + u);
        }
        CP_COMMIT();
    };

    float o[8][4];
#pragma unroll
    for (int nf = 0; nf < 8; nf++)
#pragma unroll
        for (int r = 0; r < 4; r++) o[nf][r] = 0.f;
    float m0 = -1e30f, m1 = -1e30f, l0 = 0.f, l1 = 0.f;

    const int ntiles = 2 * qt + 2;
    issue_tile(0, 0);

    for (int kt = 0; kt < ntiles; kt++) {
        if (kt + 1 < ntiles) {
            issue_tile((kt + 1) & 1, kt + 1);
            CP_WAIT1();
        } else {
            CP_WAIT0();
        }
        __syncthreads();

        char* stg = smem + (kt & 1) * ASTAGE;
        const int kbase = kt * 64;

        if (kbase <= qbase + w * 16 + 15) {
            float sfr[8][4];
#pragma unroll
            for (int nf = 0; nf < 8; nf++)
#pragma unroll
                for (int r = 0; r < 4; r++) sfr[nf][r] = 0.f;

#pragma unroll
            for (int kf = 0; kf < 4; kf++) {
#pragma unroll
                for (int nf = 0; nf < 8; nf++) {
                    int off = ((nf * 4 + kf) << 8) + (la << 3);
                    uint2 kh = *(const uint2*)(stg + off);
                    uint2 kl = *(const uint2*)(stg + 8192 + off);
                    mma16816(sfr[nf], Qh[kf], kh);
                    mma16816(sfr[nf], Qh[kf], kl);
                    mma16816(sfr[nf], Ql[kf], kh);
                }
            }

            if (kbase + 63 > qbase + w * 16) {
#pragma unroll
                for (int nf = 0; nf < 8; nf++) {
                    int c = kbase + nf * 8 + cpair;
                    if (c     > row0) sfr[nf][0] = -1e30f;
                    if (c + 1 > row0) sfr[nf][1] = -1e30f;
                    if (c     > row1) sfr[nf][2] = -1e30f;
                    if (c + 1 > row1) sfr[nf][3] = -1e30f;
                }
            }

            float mx0 = -1e30f, mx1 = -1e30f;
#pragma unroll
            for (int nf = 0; nf < 8; nf++) {
                mx0 = fmaxf(mx0, fmaxf(sfr[nf][0], sfr[nf][1]));
                mx1 = fmaxf(mx1, fmaxf(sfr[nf][2], sfr[nf][3]));
            }
            mx0 = fmaxf(mx0, __shfl_xor_sync(0xffffffffu, mx0, 1));
            mx0 = fmaxf(mx0, __shfl_xor_sync(0xffffffffu, mx0, 2));
            mx1 = fmaxf(mx1, __shfl_xor_sync(0xffffffffu, mx1, 1));
            mx1 = fmaxf(mx1, __shfl_xor_sync(0xffffffffu, mx1, 2));

            float mn0 = fmaxf(m0, mx0), mn1 = fmaxf(m1, mx1);
            float a0 = ex2(m0 - mn0), a1 = ex2(m1 - mn1);
            float s0 = 0.f, s1 = 0.f;
#pragma unroll
            for (int nf = 0; nf < 8; nf++) {
                sfr[nf][0] = ex2(sfr[nf][0] - mn0);
                sfr[nf][1] = ex2(sfr[nf][1] - mn0);
                sfr[nf][2] = ex2(sfr[nf][2] - mn1);
                sfr[nf][3] = ex2(sfr[nf][3] - mn1);
                s0 += sfr[nf][0] + sfr[nf][1];
                s1 += sfr[nf][2] + sfr[nf][3];
            }
            s0 += __shfl_xor_sync(0xffffffffu, s0, 1);
            s0 += __shfl_xor_sync(0xffffffffu, s0, 2);
            s1 += __shfl_xor_sync(0xffffffffu, s1, 1);
            s1 += __shfl_xor_sync(0xffffffffu, s1, 2);

            l0 = l0 * a0 + s0;  l1 = l1 * a1 + s1;
            m0 = mn0;           m1 = mn1;
#pragma unroll
            for (int nf = 0; nf < 8; nf++) {
                o[nf][0] *= a0; o[nf][1] *= a0;
                o[nf][2] *= a1; o[nf][3] *= a1;
            }

#pragma unroll
            for (int kf2 = 0; kf2 < 4; kf2++) {
                uint4 Ph, Pl;
                split2(make_float2(sfr[2 * kf2][0],     sfr[2 * kf2][1]),     Ph.x, Pl.x);
                split2(make_float2(sfr[2 * kf2][2],     sfr[2 * kf2][3]),     Ph.y, Pl.y);
                split2(make_float2(sfr[2 * kf2 + 1][0], sfr[2 * kf2 + 1][1]), Ph.z, Pl.z);
                split2(make_float2(sfr[2 * kf2 + 1][2], sfr[2 * kf2 + 1][3]), Ph.w, Pl.w);
#pragma unroll
                for (int nf = 0; nf < 8; nf++) {
                    int off = ((nf * 4 + kf2) << 8) + (la << 3);
                    uint2 vh = *(const uint2*)(stg + 16384 + off);
                    uint2 vl = *(const uint2*)(stg + 24576 + off);
                    mma16816(o[nf], Ph, vh);
                    mma16816(o[nf], Ph, vl);
                    mma16816(o[nf], Pl, vh);
                }
            }
        }
        __syncthreads();
    }

    float i0 = 1.f / l0, i1 = 1.f / l1;
    const int r16 = b * 128 + qt * 8 + w;
#pragma unroll
    for (int nf = 0; nf < 8; nf += 2) {
        int kfg = h * 4 + (nf >> 1);
        size_t slot = ((size_t)r16 * 64 + kfg) * 32 + la;
        uint4 ah4, al4;
        split2(make_float2(o[nf][0] * i0,     o[nf][1] * i0),     ah4.x, al4.x);
        split2(make_float2(o[nf][2] * i1,     o[nf][3] * i1),     ah4.y, al4.y);
        split2(make_float2(o[nf + 1][0] * i0, o[nf + 1][1] * i0), ah4.z, al4.z);
        split2(make_float2(o[nf + 1][2] * i1, o[nf + 1][3] * i1), ah4.w, al4.w);
        g_atAh[slot] = ah4;
        g_atAl[slot] = al4;
    }
}

// ---------------------------------------------------------------------------
// Launch
// ---------------------------------------------------------------------------
extern "C" void kernel_launch(void* const* d_in, const int* in_sizes, int n_in,
                              void* d_out, int out_size)
{
    const float* x = nullptr, *Wkqv = nullptr, *Wproj = nullptr, *bproj = nullptr;
    for (int i = 0; i < n_in; i++) {
        int sz = in_sizes[i];
        if      (sz == TB * TT * NE)      x     = (const float*)d_in[i];
        else if (sz == 3 * NE * NE)       Wkqv  = (const float*)d_in[i];
        else if (sz == NE * NE)           Wproj = (const float*)d_in[i];
        else if (sz == NE)                bproj = (const float*)d_in[i];
    }
    float* out = (float*)d_out;

    float* vtmp;
    uint4 *xAh, *xAl, *atAh, *atAl;
    uint2 *WkBh, *WkBl, *WpBh, *WpBl;
    cudaGetSymbolAddress((void**)&vtmp, g_vtmp);
    cudaGetSymbolAddress((void**)&xAh,  g_xAh);
    cudaGetSymbolAddress((void**)&xAl,  g_xAl);
    cudaGetSymbolAddress((void**)&atAh, g_atAh);
    cudaGetSymbolAddress((void**)&atAl, g_atAl);
    cudaGetSymbolAddress((void**)&WkBh, g_WkBh);
    cudaGetSymbolAddress((void**)&WkBl, g_WkBl);
    cudaGetSymbolAddress((void**)&WpBh, g_WpBh);
    cudaGetSymbolAddress((void**)&WpBl, g_WpBl);

    cudaFuncSetAttribute(gemm_bf,
                         cudaFuncAttributeMaxDynamicSharedMemorySize, GSMEM);
    cudaFuncSetAttribute(attn_mma3,
                         cudaFuncAttributeMaxDynamicSharedMemorySize, ATTN_SMEM);

    // Prep inputs: fragment-major bf16 hi/lo
    prep_a<<<2048, 256>>>(x, xAh, xAl);
    prep_b<<<3072, 256>>>(Wkqv, WkBh, WkBl);
    prep_b<<<1024, 256>>>(Wproj, WpBh, WpBl);

    // 1) KQV projection, fused epilogue -> Q/K frag planes + V fp32
    {
        dim3 grid(C3 / 128, 32);
        gemm_bf<<<grid, 128, GSMEM>>>(xAh, xAl, WkBh, WkBl, nullptr, vtmp, NE, 1);
    }

    // 1b) V fragment plane
    prep_v<<<4096, 256>>>();

    // 2) Causal flash attention -> g_atA planes
    {
        dim3 grid(TT / 128, NH, TB);
        attn_mma3<<<grid, 256, ATTN_SMEM>>>();
    }

    // 3) Output projection + bias
    {
        dim3 grid(NE / 128, 32);
        gemm_bf<<<grid, 128, GSMEM>>>(atAh, atAl, WpBh, WpBl, bproj, out, NE, 0);
    }
}